// round 10
// baseline (speedup 1.0000x reference)
#include <cuda_runtime.h>
#include <cuda_bf16.h>
#include <cstdint>

// ---------------------------------------------------------------------------
// AttentionGNN Round 9 (from R8):
//   - NEW hmma_wide: 512-thread CTA 128x256 NT bf16 GEMM, 16 warps (2m x 8n),
//     warp tile 64x32, 3-stage cp.async pipeline. 4 warps/SMSP hides the
//     LDSM->MMA RAW latency that capped pass 4 at ~68% tensor busy.
//   - pass 4 AND pass 2 both use hmma_wide (pass 2: kIters=4, bf16 out).
//   everything else unchanged from R8.
// ---------------------------------------------------------------------------

#define B_   8
#define N_   2048
#define D_   256

typedef __nv_bfloat16 bf16;

// Scratch (device globals)
__device__ bf16  g_texth[(size_t)B_ * N_ * D_];
__device__ bf16  g_textl[(size_t)B_ * N_ * D_];
__device__ bf16  g_wth[3 * D_ * D_];
__device__ bf16  g_wtl[3 * D_ * D_];
__device__ bf16  g_qkb[(size_t)B_ * N_ * 512];
__device__ float g_v  [(size_t)B_ * N_ * D_];
__device__ float g_vt [(size_t)B_ * D_ * N_];
__device__ float g_s  [(size_t)B_ * N_ * N_];
__device__ bf16  g_attn[(size_t)B_ * N_ * N_];
__device__ bf16  g_adjT[(size_t)B_ * N_ * N_];

// ===========================================================================
// helpers
// ===========================================================================
__device__ __forceinline__ uint32_t smem_u32(const void* p) {
    uint32_t a;
    asm("{ .reg .u64 t; cvta.to.shared.u64 t, %1; cvt.u32.u64 %0, t; }"
        : "=r"(a) : "l"(p));
    return a;
}

#define SMEM_SWIZZLE_128B(off) ((off) ^ (((off) >> 3) & 0x70))

#define CP_ASYNC_16(dst, src) \
    asm volatile("cp.async.cg.shared.global [%0], [%1], 16;" \
                 :: "r"(dst), "l"(src) : "memory")
#define CP_ASYNC_COMMIT() asm volatile("cp.async.commit_group;" ::: "memory")
#define CP_ASYNC_WAIT_ALL() asm volatile("cp.async.wait_group 0;" ::: "memory")
#define CP_ASYNC_WAIT_1()  asm volatile("cp.async.wait_group 1;" ::: "memory")

#define LDMATRIX_X4(r0, r1, r2, r3, addr) \
    asm volatile("ldmatrix.sync.aligned.m8n8.x4.shared.b16 {%0,%1,%2,%3}, [%4];" \
                 : "=r"(r0), "=r"(r1), "=r"(r2), "=r"(r3) : "r"(addr))

#define MMA_BF16(d, a, b) \
    asm volatile("mma.sync.aligned.m16n8k16.row.col.f32.bf16.bf16.f32 " \
                 "{%0,%1,%2,%3}, {%4,%5,%6,%7}, {%8,%9}, {%0,%1,%2,%3};" \
                 : "+f"((d)[0]), "+f"((d)[1]), "+f"((d)[2]), "+f"((d)[3]) \
                 : "r"((a)[0]), "r"((a)[1]), "r"((a)[2]), "r"((a)[3]), \
                   "r"((b)[0]), "r"((b)[1]))

#define MMA_TF32(d, a, b) \
    asm volatile("mma.sync.aligned.m16n8k8.row.col.f32.tf32.tf32.f32 " \
                 "{%0,%1,%2,%3}, {%4,%5,%6,%7}, {%8,%9}, {%0,%1,%2,%3};" \
                 : "+f"((d)[0]), "+f"((d)[1]), "+f"((d)[2]), "+f"((d)[3]) \
                 : "r"((a)[0]), "r"((a)[1]), "r"((a)[2]), "r"((a)[3]), \
                   "r"((b)[0]), "r"((b)[1]))

__device__ __forceinline__ uint32_t f2tf32(float f) {
    uint32_t r;
    asm("cvt.rna.tf32.f32 %0, %1;" : "=r"(r) : "f"(f));
    return r;
}

#define HTILE 16384

template <int ROWS, int THREADS = 256>
__device__ __forceinline__ void load_tileR(
    uint32_t s, const char* gbase, int ldBytes, int tid)
{
    #pragma unroll
    for (int i = 0; i < ROWS * 8 / THREADS; ++i) {
        int id  = tid + THREADS * i;
        int row = id >> 3;
        int c   = (id & 7) * 16;
        CP_ASYNC_16(s + SMEM_SWIZZLE_128B(row * 128 + c),
                    gbase + (size_t)row * ldBytes + c);
    }
}

__device__ __forceinline__ void store2(float* p, float a, float b) {
    *(float2*)p = make_float2(a, b);
}
__device__ __forceinline__ void store2(bf16* p, float a, float b) {
    __nv_bfloat162 h;
    h.x = __float2bfloat16(a);
    h.y = __float2bfloat16(b);
    *(__nv_bfloat162*)p = h;
}

// ===========================================================================
// hmma_wide: 512-thread NT bf16 GEMM, CTA 128(m) x 256(n), K-chunk 64.
// 16 warps: 2(m) x 8(n); warp tile 64x32. 3-stage cp.async pipeline.
// C[b][m][n] = sum_k A[b][m][k] * Bt[b][n][k]
// ===========================================================================
#define PW_AT 16384
#define PW_BT 32768
#define PW_BUF (PW_AT + PW_BT)
#define SMEM_PW (3 * PW_BUF + 1024)

template <typename OutT>
__global__ void __launch_bounds__(512)
hmma_wide(const bf16* __restrict__ A, const bf16* __restrict__ Bt,
          OutT* __restrict__ C,
          int kIters, int ldA, int ldB, int ldC,
          long long sA, long long sB, long long sC)
{
    extern __shared__ char dsm[];
    const uint32_t base = (smem_u32(dsm) + 1023) & ~1023u;

    const int tid  = threadIdx.x;
    const int lane = tid & 31;
    const int wid  = tid >> 5;             // 0..15
    const int wm0  = (wid & 1) * 64;
    const int wn0  = (wid >> 1) * 32;      // 0..7 -> 0..224
    const int lr   = lane & 15;
    const int lc   = lane >> 4;

    const int b  = blockIdx.z;
    const int m0 = blockIdx.y * 128;
    const int n0 = blockIdx.x * 256;
    const char* Ab = (const char*)(A  + (size_t)b * sA + (size_t)m0 * ldA);
    const char* Bb = (const char*)(Bt + (size_t)b * sB + (size_t)n0 * ldB);
    const int ldAB = ldA * 2;
    const int ldBB = ldB * 2;

    float acc[4][4][4];
    #pragma unroll
    for (int i = 0; i < 4; ++i)
        #pragma unroll
        for (int j = 0; j < 4; ++j)
            #pragma unroll
            for (int r = 0; r < 4; ++r) acc[i][j][r] = 0.0f;

    // prologue: stages 0,1 in flight
    load_tileR<128, 512>(base,         Ab, ldAB, tid);
    load_tileR<256, 512>(base + PW_AT, Bb, ldBB, tid);
    CP_ASYNC_COMMIT();
    if (kIters > 1) {
        load_tileR<128, 512>(base + PW_BUF,         Ab + 128, ldAB, tid);
        load_tileR<256, 512>(base + PW_BUF + PW_AT, Bb + 128, ldBB, tid);
    }
    CP_ASYNC_COMMIT();

    for (int kt = 0; kt < kIters; ++kt) {
        if (kt + 1 < kIters) { CP_ASYNC_WAIT_1(); } else { CP_ASYNC_WAIT_ALL(); }
        __syncthreads();

        if (kt + 2 < kIters) {
            const uint32_t nx = base + ((kt + 2) % 3) * PW_BUF;
            const size_t ko = (size_t)(kt + 2) * 128;
            load_tileR<128, 512>(nx,         Ab + ko, ldAB, tid);
            load_tileR<256, 512>(nx + PW_AT, Bb + ko, ldBB, tid);
            CP_ASYNC_COMMIT();
        } else {
            CP_ASYNC_COMMIT();   // keep group count aligned with waits
        }

        const uint32_t cA = base + (kt % 3) * PW_BUF;
        const uint32_t cB = cA + PW_AT;

        #pragma unroll
        for (int ks = 0; ks < 4; ++ks) {
            uint32_t af[4][4];
            uint32_t bfr[4][2];
            const int csel = ks * 2 + lc;

            #pragma unroll
            for (int mi = 0; mi < 4; ++mi) {
                const int row = wm0 + mi * 16 + lr;
                LDMATRIX_X4(af[mi][0], af[mi][1], af[mi][2], af[mi][3],
                            cA + SMEM_SWIZZLE_128B(row * 128 + csel * 16));
            }
            #pragma unroll
            for (int nb = 0; nb < 2; ++nb) {
                const int row = wn0 + nb * 16 + lr;
                uint32_t r0, r1, r2, r3;
                LDMATRIX_X4(r0, r1, r2, r3,
                            cB + SMEM_SWIZZLE_128B(row * 128 + csel * 16));
                bfr[nb * 2][0]     = r0;  bfr[nb * 2][1]     = r2;
                bfr[nb * 2 + 1][0] = r1;  bfr[nb * 2 + 1][1] = r3;
            }

            #pragma unroll
            for (int mi = 0; mi < 4; ++mi)
                #pragma unroll
                for (int nj = 0; nj < 4; ++nj)
                    MMA_BF16(acc[mi][nj], af[mi], bfr[nj]);
        }
    }

    const size_t crow = (size_t)b * sC + (size_t)(m0 + wm0) * ldC + n0 + wn0;
    const int r     = lane >> 2;
    const int cpair = (lane & 3) * 2;
    #pragma unroll
    for (int mi = 0; mi < 4; ++mi) {
        #pragma unroll
        for (int nj = 0; nj < 4; ++nj) {
            const size_t off0 = crow + (size_t)(mi * 16 + r) * ldC + nj * 8 + cpair;
            store2(C + off0, acc[mi][nj][0], acc[mi][nj][1]);
            store2(C + off0 + (size_t)8 * ldC, acc[mi][nj][2], acc[mi][nj][3]);
        }
    }
}

// ===========================================================================
// Generic NT bf16 HMMA GEMM, CTA 128x128 (projections; unchanged from R8)
// ===========================================================================
template <int TERMS, int BIAS, typename OutT>
__global__ void __launch_bounds__(256, TERMS == 1 ? 2 : 1)
hmma_g(const bf16* __restrict__ Ah, const bf16* __restrict__ Al,
       const bf16* __restrict__ Bh, const bf16* __restrict__ Bl,
       const float* __restrict__ bias, const float* __restrict__ bias2,
       OutT* __restrict__ C,
       int kIters, int ldA, int ldB, int ldC,
       long long sA, long long sB, long long sC)
{
    extern __shared__ char dsm[];
    const uint32_t base = (smem_u32(dsm) + 1023) & ~1023u;
    constexpr int TPB = (TERMS == 1) ? 2 : (TERMS == 2 ? 3 : 4);
    constexpr uint32_t OAL = HTILE;
    constexpr uint32_t OBH = (TERMS == 1) ? HTILE : 2u * HTILE;
    constexpr uint32_t OBL = 3u * HTILE;

    const int tid  = threadIdx.x;
    const int lane = tid & 31;
    const int wid  = tid >> 5;
    const int wm0  = (wid & 1) * 64;
    const int wn0  = (wid >> 1) * 32;
    const int lr   = lane & 15;
    const int lc   = lane >> 4;

    const int b  = blockIdx.z;
    const int m0 = blockIdx.y * 128;
    const int n0 = blockIdx.x * 128;
    const char* Ahb = (const char*)(Ah + (size_t)b * sA + (size_t)m0 * ldA);
    const char* Alb = (TERMS >= 2)
        ? (const char*)(Al + (size_t)b * sA + (size_t)m0 * ldA) : nullptr;
    const char* Bhb = (const char*)(Bh + (size_t)b * sB + (size_t)n0 * ldB);
    const char* Blb = (TERMS == 3)
        ? (const char*)(Bl + (size_t)b * sB + (size_t)n0 * ldB) : nullptr;
    const int ldAB = ldA * 2;
    const int ldBB = ldB * 2;

    float acc[4][4][4];
    #pragma unroll
    for (int i = 0; i < 4; ++i)
        #pragma unroll
        for (int j = 0; j < 4; ++j)
            #pragma unroll
            for (int r = 0; r < 4; ++r) acc[i][j][r] = 0.0f;

    load_tileR<128>(base, Ahb, ldAB, tid);
    if (TERMS >= 2) load_tileR<128>(base + OAL, Alb, ldAB, tid);
    load_tileR<128>(base + OBH, Bhb, ldBB, tid);
    if (TERMS == 3) load_tileR<128>(base + OBL, Blb, ldBB, tid);
    CP_ASYNC_COMMIT();
    CP_ASYNC_WAIT_ALL();
    __syncthreads();

    for (int kt = 0; kt < kIters; ++kt) {
        const int buf = kt & 1;
        const uint32_t cAh = base + buf * (TPB * HTILE);
        const uint32_t cAl = cAh + OAL;
        const uint32_t cBh = cAh + OBH;
        const uint32_t cBl = cAh + OBL;

        if (kt + 1 < kIters) {
            const uint32_t nx = base + (buf ^ 1) * (TPB * HTILE);
            const size_t ko = (size_t)(kt + 1) * 128;
            load_tileR<128>(nx, Ahb + ko, ldAB, tid);
            if (TERMS >= 2) load_tileR<128>(nx + OAL, Alb + ko, ldAB, tid);
            load_tileR<128>(nx + OBH, Bhb + ko, ldBB, tid);
            if (TERMS == 3) load_tileR<128>(nx + OBL, Blb + ko, ldBB, tid);
            CP_ASYNC_COMMIT();
        }

        #pragma unroll
        for (int ks = 0; ks < 4; ++ks) {
            uint32_t afh[4][4], afl[4][4];
            uint32_t bfh[4][2], bfl[4][2];
            const int csel = ks * 2 + lc;

            #pragma unroll
            for (int mi = 0; mi < 4; ++mi) {
                const int row = wm0 + mi * 16 + lr;
                const uint32_t so = SMEM_SWIZZLE_128B(row * 128 + csel * 16);
                LDMATRIX_X4(afh[mi][0], afh[mi][1], afh[mi][2], afh[mi][3], cAh + so);
                if (TERMS >= 2)
                    LDMATRIX_X4(afl[mi][0], afl[mi][1], afl[mi][2], afl[mi][3], cAl + so);
            }
            #pragma unroll
            for (int nb = 0; nb < 2; ++nb) {
                const int row = wn0 + nb * 16 + lr;
                const uint32_t so = SMEM_SWIZZLE_128B(row * 128 + csel * 16);
                uint32_t r0, r1, r2, r3;
                LDMATRIX_X4(r0, r1, r2, r3, cBh + so);
                bfh[nb * 2][0]     = r0;  bfh[nb * 2][1]     = r2;
                bfh[nb * 2 + 1][0] = r1;  bfh[nb * 2 + 1][1] = r3;
                if (TERMS == 3) {
                    LDMATRIX_X4(r0, r1, r2, r3, cBl + so);
                    bfl[nb * 2][0]     = r0;  bfl[nb * 2][1]     = r2;
                    bfl[nb * 2 + 1][0] = r1;  bfl[nb * 2 + 1][1] = r3;
                }
            }

            #pragma unroll
            for (int mi = 0; mi < 4; ++mi)
                #pragma unroll
                for (int nj = 0; nj < 4; ++nj) {
                    MMA_BF16(acc[mi][nj], afh[mi], bfh[nj]);
                    if (TERMS >= 2) MMA_BF16(acc[mi][nj], afl[mi], bfh[nj]);
                    if (TERMS == 3) MMA_BF16(acc[mi][nj], afh[mi], bfl[nj]);
                }
        }

        CP_ASYNC_WAIT_ALL();
        __syncthreads();
    }

    const size_t crow = (size_t)b * sC + (size_t)(m0 + wm0) * ldC + n0 + wn0;
    const int r     = lane >> 2;
    const int cpair = (lane & 3) * 2;
    const float* bp = (BIAS && n0 >= 256) ? bias2 : bias;
    const int cbase = (n0 & 255) + wn0;
    #pragma unroll
    for (int mi = 0; mi < 4; ++mi) {
        #pragma unroll
        for (int nj = 0; nj < 4; ++nj) {
            float v0 = acc[mi][nj][0], v1 = acc[mi][nj][1];
            float v2 = acc[mi][nj][2], v3 = acc[mi][nj][3];
            if (BIAS) {
                const int col = cbase + nj * 8 + cpair;
                const float b0 = bp[col], b1 = bp[col + 1];
                v0 += b0; v1 += b1; v2 += b0; v3 += b1;
            }
            const size_t off0 = crow + (size_t)(mi * 16 + r) * ldC + nj * 8 + cpair;
            store2(C + off0, v0, v1);
            store2(C + off0 + (size_t)8 * ldC, v2, v3);
        }
    }
}

// ===========================================================================
// Pass 5: tf32 mma (unchanged from R8)
// ===========================================================================
#define P5T_STRIDE 68
#define P5T_TILE  (128 * P5T_STRIDE * 4)
#define P5T_BUF   (2 * P5T_TILE)
#define SMEM_P5T  (2 * P5T_BUF + 1024)

__global__ void __launch_bounds__(256)
tmma_out(const float* __restrict__ A,
         const float* __restrict__ Bt,
         float* __restrict__ C)
{
    extern __shared__ char dsm[];
    const uint32_t base = (smem_u32(dsm) + 1023) & ~1023u;
    char* dbase = dsm + (base - smem_u32(dsm));

    const int tid  = threadIdx.x;
    const int lane = tid & 31;
    const int wid  = tid >> 5;
    const int wm0  = (wid & 1) * 64;
    const int wn0  = (wid >> 1) * 32;
    const int lg   = lane >> 2;
    const int lt   = lane & 3;

    const int b  = blockIdx.z;
    const int m0 = blockIdx.y * 128;
    const int n0 = blockIdx.x * 128;
    const char* Ab  = (const char*)(A  + ((size_t)b * N_ + m0) * N_);
    const char* Bb  = (const char*)(Bt + ((size_t)b * D_ + n0) * N_);
    const int ldAB = N_ * 4;

    float4 ar[8];

    auto ldg_A = [&](int kt) {
        #pragma unroll
        for (int i = 0; i < 8; ++i) {
            const int id  = tid + 256 * i;
            const int row = id >> 4;
            const int c16 = id & 15;
            ar[i] = *(const float4*)(Ab + (size_t)row * ldAB
                                        + (size_t)kt * 256 + c16 * 16);
        }
    };
    auto sts_A = [&](int buf) {
        uint32_t* sA = (uint32_t*)(dbase + buf * P5T_BUF);
        #pragma unroll
        for (int i = 0; i < 8; ++i) {
            const int id  = tid + 256 * i;
            const int row = id >> 4;
            const int c16 = id & 15;
            uint4 t;
            t.x = f2tf32(ar[i].x);
            t.y = f2tf32(ar[i].y);
            t.z = f2tf32(ar[i].z);
            t.w = f2tf32(ar[i].w);
            *(uint4*)(sA + row * P5T_STRIDE + c16 * 4) = t;
        }
    };
    auto ldB = [&](int buf, int kt) {
        const uint32_t sB = base + buf * P5T_BUF + P5T_TILE;
        const char* g = Bb + (size_t)kt * 256;
        #pragma unroll
        for (int i = 0; i < 8; ++i) {
            const int id  = tid + 256 * i;
            const int row = id >> 4;
            const int c16 = id & 15;
            CP_ASYNC_16(sB + row * (P5T_STRIDE * 4) + c16 * 16,
                        g + (size_t)row * ldAB + c16 * 16);
        }
    };

    float acc[4][4][4];
    #pragma unroll
    for (int i = 0; i < 4; ++i)
        #pragma unroll
        for (int j = 0; j < 4; ++j)
            #pragma unroll
            for (int r = 0; r < 4; ++r) acc[i][j][r] = 0.0f;

    ldB(0, 0);
    CP_ASYNC_COMMIT();
    ldg_A(0);
    sts_A(0);
    CP_ASYNC_WAIT_ALL();
    __syncthreads();

    const int KITER = N_ / 64;
    for (int kt = 0; kt < KITER; ++kt) {
        const int buf = kt & 1;
        const uint32_t* sA = (const uint32_t*)(dbase + buf * P5T_BUF);
        const float*    sB = (const float*)(dbase + buf * P5T_BUF + P5T_TILE);

        if (kt + 1 < KITER) {
            ldB(buf ^ 1, kt + 1);
            CP_ASYNC_COMMIT();
            ldg_A(kt + 1);
        }

        #pragma unroll
        for (int s = 0; s < 8; ++s) {
            const int k0 = s * 8;
            uint32_t af[4][4];
            uint32_t bf[4][2];

            #pragma unroll
            for (int mi = 0; mi < 4; ++mi) {
                const int rb = (wm0 + mi * 16 + lg) * P5T_STRIDE + k0 + lt;
                af[mi][0] = sA[rb];
                af[mi][1] = sA[rb + 8 * P5T_STRIDE];
                af[mi][2] = sA[rb + 4];
                af[mi][3] = sA[rb + 8 * P5T_STRIDE + 4];
            }
            #pragma unroll
            for (int nj = 0; nj < 4; ++nj) {
                const int rb = (wn0 + nj * 8 + lg) * P5T_STRIDE + k0 + lt;
                bf[nj][0] = f2tf32(sB[rb]);
                bf[nj][1] = f2tf32(sB[rb + 4]);
            }

            #pragma unroll
            for (int mi = 0; mi < 4; ++mi)
                #pragma unroll
                for (int nj = 0; nj < 4; ++nj)
                    MMA_TF32(acc[mi][nj], af[mi], bf[nj]);
        }

        if (kt + 1 < KITER) {
            __syncthreads();
            sts_A(buf ^ 1);
            CP_ASYNC_WAIT_ALL();
            __syncthreads();
        }
    }

    float* Cb = C + ((size_t)b * N_ + m0 + wm0) * D_ + n0 + wn0;
    const int cpair = lt * 2;
    #pragma unroll
    for (int mi = 0; mi < 4; ++mi) {
        #pragma unroll
        for (int nj = 0; nj < 4; ++nj) {
            float* p = Cb + (size_t)(mi * 16 + lg) * D_ + nj * 8 + cpair;
            *(float2*)p            = make_float2(acc[mi][nj][0], acc[mi][nj][1]);
            *(float2*)(p + 8 * D_) = make_float2(acc[mi][nj][2], acc[mi][nj][3]);
        }
    }
}

// ===========================================================================
// small kernels (unchanged from R8)
// ===========================================================================
__global__ __launch_bounds__(256)
void split_f32(const float* __restrict__ X, bf16* __restrict__ H,
               bf16* __restrict__ L, size_t n4)
{
    size_t i = (size_t)blockIdx.x * blockDim.x + threadIdx.x;
    if (i >= n4) return;
    float4 v = ((const float4*)X)[i];
    float f[4] = {v.x, v.y, v.z, v.w};
    __nv_bfloat162 hh[2], ll[2];
    #pragma unroll
    for (int j = 0; j < 2; ++j) {
        bf16 h0 = __float2bfloat16(f[2 * j]);
        bf16 h1 = __float2bfloat16(f[2 * j + 1]);
        hh[j].x = h0; hh[j].y = h1;
        ll[j].x = __float2bfloat16(f[2 * j]     - __bfloat162float(h0));
        ll[j].y = __float2bfloat16(f[2 * j + 1] - __bfloat162float(h1));
    }
    ((uint2*)H)[i] = *(uint2*)hh;
    ((uint2*)L)[i] = *(uint2*)ll;
}

__global__ __launch_bounds__(256)
void wtrans_split3(const float* __restrict__ W0, const float* __restrict__ W1,
                   const float* __restrict__ W2,
                   bf16* __restrict__ Th, bf16* __restrict__ Tl)
{
    __shared__ float t[32][33];
    const int z = blockIdx.z;
    const float* W = (z == 0) ? W0 : (z == 1) ? W1 : W2;
    bf16* Thz = Th + z * D_ * D_;
    bf16* Tlz = Tl + z * D_ * D_;
    const int x0 = blockIdx.x * 32;
    const int y0 = blockIdx.y * 32;
    const int tx = threadIdx.x & 31;
    const int ty = threadIdx.x >> 5;
    #pragma unroll
    for (int j = 0; j < 4; ++j)
        t[ty + 8 * j][tx] = W[(y0 + ty + 8 * j) * D_ + x0 + tx];
    __syncthreads();
    #pragma unroll
    for (int j = 0; j < 4; ++j) {
        float val = t[tx][ty + 8 * j];
        bf16 hi = __float2bfloat16(val);
        const int off = (x0 + ty + 8 * j) * D_ + y0 + tx;
        Thz[off] = hi;
        Tlz[off] = __float2bfloat16(val - __bfloat162float(hi));
    }
}

__global__ __launch_bounds__(256)
void softmax_warp(const bf16* __restrict__ S, bf16* __restrict__ O, float scale)
{
    const int lane = threadIdx.x & 31;
    const int w    = threadIdx.x >> 5;
    const size_t row = (size_t)blockIdx.x * 8 + w;
    const uint4* p = (const uint4*)(S + row * N_);
    uint4* o       = (uint4*)(O + row * N_);

    float vals[64];
    float m = -1e30f;
    #pragma unroll
    for (int c = 0; c < 8; ++c) {
        uint4 raw = p[c * 32 + lane];
        __nv_bfloat162* pr = (__nv_bfloat162*)&raw;
        #pragma unroll
        for (int i = 0; i < 4; ++i) {
            float2 f = __bfloat1622float2(pr[i]);
            vals[c * 8 + 2 * i]     = f.x * scale;
            vals[c * 8 + 2 * i + 1] = f.y * scale;
            m = fmaxf(m, fmaxf(f.x * scale, f.y * scale));
        }
    }
    #pragma unroll
    for (int s = 16; s > 0; s >>= 1)
        m = fmaxf(m, __shfl_xor_sync(0xFFFFFFFFu, m, s));

    float sum = 0.0f;
    #pragma unroll
    for (int i = 0; i < 64; ++i) {
        vals[i] = __expf(vals[i] - m);
        sum += vals[i];
    }
    #pragma unroll
    for (int s = 16; s > 0; s >>= 1)
        sum += __shfl_xor_sync(0xFFFFFFFFu, sum, s);
    const float inv = 1.0f / sum;

    #pragma unroll
    for (int c = 0; c < 8; ++c) {
        uint4 outv;
        __nv_bfloat162* po = (__nv_bfloat162*)&outv;
        #pragma unroll
        for (int i = 0; i < 4; ++i) {
            po[i].x = __float2bfloat16(vals[c * 8 + 2 * i] * inv);
            po[i].y = __float2bfloat16(vals[c * 8 + 2 * i + 1] * inv);
        }
        o[c * 32 + lane] = outv;
    }
}

__global__ __launch_bounds__(256)
void transpose_bf16(const float* __restrict__ A, bf16* __restrict__ T)
{
    __shared__ float t[32][33];
    const int b  = blockIdx.z;
    const int x0 = blockIdx.x * 32;
    const int y0 = blockIdx.y * 32;
    const float* Ab = A + (size_t)b * N_ * N_;
    bf16* Tb = T + (size_t)b * N_ * N_;
    const int tx = threadIdx.x & 31;
    const int ty = threadIdx.x >> 5;
    #pragma unroll
    for (int j = 0; j < 4; ++j)
        t[ty + 8 * j][tx] = Ab[(size_t)(y0 + ty + 8 * j) * N_ + x0 + tx];
    __syncthreads();
    #pragma unroll
    for (int j = 0; j < 4; ++j)
        Tb[(size_t)(x0 + ty + 8 * j) * N_ + y0 + tx] =
            __float2bfloat16(t[tx][ty + 8 * j]);
}

__global__ __launch_bounds__(256)
void transpose_f32(const float* __restrict__ A, float* __restrict__ T)
{
    __shared__ float t[32][33];
    const int b  = blockIdx.z;
    const int x0 = blockIdx.x * 32;
    const int y0 = blockIdx.y * 32;
    const float* Ab = A + (size_t)b * N_ * D_;
    float* Tb = T + (size_t)b * D_ * N_;
    const int tx = threadIdx.x & 31;
    const int ty = threadIdx.x >> 5;
    #pragma unroll
    for (int j = 0; j < 4; ++j)
        t[ty + 8 * j][tx] = Ab[(size_t)(y0 + ty + 8 * j) * D_ + x0 + tx];
    __syncthreads();
    #pragma unroll
    for (int j = 0; j < 4; ++j)
        Tb[(size_t)(x0 + ty + 8 * j) * N_ + y0 + tx] = t[tx][ty + 8 * j];
}

// ===========================================================================
extern "C" void kernel_launch(void* const* d_in, const int* in_sizes, int n_in,
                              void* d_out, int out_size)
{
    const float* text = (const float*)d_in[0];
    const float* adj  = (const float*)d_in[1];
    const float* Wq   = (const float*)d_in[2];
    const float* bq   = (const float*)d_in[3];
    const float* Wk   = (const float*)d_in[4];
    const float* bk   = (const float*)d_in[5];
    const float* Wv   = (const float*)d_in[6];
    const float* bv   = (const float*)d_in[7];

    float* out     = (float*)d_out;
    float* new_adj = out + (long long)B_ * N_ * D_;

    bf16 *pth, *ptl, *pwth, *pwtl, *pqk, *pattn, *padjT;
    float *pv, *pvt, *ps;
    cudaGetSymbolAddress((void**)&pth,  g_texth);
    cudaGetSymbolAddress((void**)&ptl,  g_textl);
    cudaGetSymbolAddress((void**)&pwth, g_wth);
    cudaGetSymbolAddress((void**)&pwtl, g_wtl);
    cudaGetSymbolAddress((void**)&pqk,  g_qkb);
    cudaGetSymbolAddress((void**)&pv,   g_v);
    cudaGetSymbolAddress((void**)&pvt,  g_vt);
    cudaGetSymbolAddress((void**)&ps,   g_s);
    cudaGetSymbolAddress((void**)&pattn, g_attn);
    cudaGetSymbolAddress((void**)&padjT, g_adjT);

    bf16* psb = (bf16*)ps;

    const int SMEM_G2 = 2 * 3 * HTILE + 1024;
    const int SMEM_G3 = 2 * 4 * HTILE + 1024;
    cudaFuncSetAttribute((const void*)hmma_g<2, 1, bf16>,
                         cudaFuncAttributeMaxDynamicSharedMemorySize, SMEM_G2);
    cudaFuncSetAttribute((const void*)hmma_g<3, 1, float>,
                         cudaFuncAttributeMaxDynamicSharedMemorySize, SMEM_G3);
    cudaFuncSetAttribute((const void*)hmma_wide<float>,
                         cudaFuncAttributeMaxDynamicSharedMemorySize, SMEM_PW);
    cudaFuncSetAttribute((const void*)hmma_wide<bf16>,
                         cudaFuncAttributeMaxDynamicSharedMemorySize, SMEM_PW);
    cudaFuncSetAttribute((const void*)tmma_out,
                         cudaFuncAttributeMaxDynamicSharedMemorySize, SMEM_P5T);

    const dim3 t(256);
    const dim3 t512(512);
    const long long sQK = (long long)N_ * 512;
    const long long sS  = (long long)N_ * N_;

    // pre: split text; transpose+split all 3 weights
    {
        const size_t n4 = (size_t)B_ * N_ * D_ / 4;
        split_f32<<<(unsigned)((n4 + 255) / 256), t>>>(text, pth, ptl, n4);
        dim3 g(D_ / 32, D_ / 32, 3);
        wtrans_split3<<<g, t>>>(Wq, Wk, Wv, pwth, pwtl);
    }

    // adjT (independent)
    {
        dim3 g(N_ / 32, N_ / 32, B_);
        transpose_bf16<<<g, t>>>(adj, padjT);
    }

    // pass 1: fused q|k projection; v projection
    {
        dim3 gqk(512 / 128, (B_ * N_) / 128, 1);
        hmma_g<2, 1, bf16><<<gqk, t, SMEM_G2>>>(
            pth, ptl, pwth, nullptr, bq, bk, pqk,
            D_ / 64, D_, D_, 512, 0, 0, 0);
        dim3 gv(D_ / 128, (B_ * N_) / 128, 1);
        hmma_g<3, 1, float><<<gv, t, SMEM_G3>>>(
            pth, ptl, pwth + 2 * D_ * D_, pwtl + 2 * D_ * D_, bv, nullptr, pv,
            D_ / 64, D_, D_, D_, 0, 0, 0);
    }

    // v^T fp32
    {
        dim3 g(D_ / 32, N_ / 32, B_);
        transpose_f32<<<g, t>>>(pv, pvt);
    }

    // pass 2: S = q @ k^T -> bf16 (wide kernel, kIters=4)
    {
        dim3 g(N_ / 256, N_ / 128, B_);   // (8, 16, 8)
        hmma_wide<bf16><<<g, t512, SMEM_PW>>>(
            pqk, pqk + 256, psb, D_ / 64, 512, 512, N_, sQK, sQK, sS);
    }

    // pass 3: softmax (warp per row)
    softmax_warp<<<B_ * N_ / 8, t>>>(psb, pattn, 1.0f / 16.0f);

    // pass 4: new_adj = attn @ adjT^T (wide kernel)
    {
        dim3 g(N_ / 256, N_ / 128, B_);   // (8, 16, 8)
        hmma_wide<float><<<g, t512, SMEM_PW>>>(
            pattn, padjT, new_adj, N_ / 64, N_, N_, N_, sS, sS, sS);
    }

    // pass 5: out = new_adj @ vT^T  (tf32)
    {
        dim3 g(D_ / 128, N_ / 128, B_);
        tmma_out<<<g, t, SMEM_P5T>>>(new_adj, pvt, out);
    }
}

// round 11
// speedup vs baseline: 1.0038x; 1.0038x over previous
#include <cuda_runtime.h>
#include <cuda_bf16.h>
#include <cstdint>

// ---------------------------------------------------------------------------
// AttentionGNN Round 10 = R8 (best: 737.8us) + fused QKV projection:
//   - ONE hmma_qkv launch computes q,k (bf16, cols 0..511 of qk buffer) and
//     v (fp32) against concatenated WqT|WkT|WvT, 3-term double-bf16.
//   - bias concat [bq|bk|bv] built inside wtrans_split3.
//   - R9's 512-thread wide kernel REVERTED (regressed 738->750).
// ---------------------------------------------------------------------------

#define B_   8
#define N_   2048
#define D_   256

typedef __nv_bfloat16 bf16;

// Scratch (device globals)
__device__ bf16  g_texth[(size_t)B_ * N_ * D_];
__device__ bf16  g_textl[(size_t)B_ * N_ * D_];
__device__ bf16  g_wth[3 * D_ * D_];            // WqT|WkT|WvT hi (768x256)
__device__ bf16  g_wtl[3 * D_ * D_];
__device__ float g_bias[3 * D_];                // bq|bk|bv
__device__ bf16  g_qkb[(size_t)B_ * N_ * 512];  // q|k per row
__device__ float g_v  [(size_t)B_ * N_ * D_];
__device__ float g_vt [(size_t)B_ * D_ * N_];
__device__ float g_s  [(size_t)B_ * N_ * N_];
__device__ bf16  g_attn[(size_t)B_ * N_ * N_];
__device__ bf16  g_adjT[(size_t)B_ * N_ * N_];

// ===========================================================================
// helpers
// ===========================================================================
__device__ __forceinline__ uint32_t smem_u32(const void* p) {
    uint32_t a;
    asm("{ .reg .u64 t; cvta.to.shared.u64 t, %1; cvt.u32.u64 %0, t; }"
        : "=r"(a) : "l"(p));
    return a;
}

#define SMEM_SWIZZLE_128B(off) ((off) ^ (((off) >> 3) & 0x70))

#define CP_ASYNC_16(dst, src) \
    asm volatile("cp.async.cg.shared.global [%0], [%1], 16;" \
                 :: "r"(dst), "l"(src) : "memory")
#define CP_ASYNC_COMMIT() asm volatile("cp.async.commit_group;" ::: "memory")
#define CP_ASYNC_WAIT_ALL() asm volatile("cp.async.wait_group 0;" ::: "memory")
#define CP_ASYNC_WAIT_1()  asm volatile("cp.async.wait_group 1;" ::: "memory")

#define LDMATRIX_X4(r0, r1, r2, r3, addr) \
    asm volatile("ldmatrix.sync.aligned.m8n8.x4.shared.b16 {%0,%1,%2,%3}, [%4];" \
                 : "=r"(r0), "=r"(r1), "=r"(r2), "=r"(r3) : "r"(addr))

#define MMA_BF16(d, a, b) \
    asm volatile("mma.sync.aligned.m16n8k16.row.col.f32.bf16.bf16.f32 " \
                 "{%0,%1,%2,%3}, {%4,%5,%6,%7}, {%8,%9}, {%0,%1,%2,%3};" \
                 : "+f"((d)[0]), "+f"((d)[1]), "+f"((d)[2]), "+f"((d)[3]) \
                 : "r"((a)[0]), "r"((a)[1]), "r"((a)[2]), "r"((a)[3]), \
                   "r"((b)[0]), "r"((b)[1]))

#define MMA_TF32(d, a, b) \
    asm volatile("mma.sync.aligned.m16n8k8.row.col.f32.tf32.tf32.f32 " \
                 "{%0,%1,%2,%3}, {%4,%5,%6,%7}, {%8,%9}, {%0,%1,%2,%3};" \
                 : "+f"((d)[0]), "+f"((d)[1]), "+f"((d)[2]), "+f"((d)[3]) \
                 : "r"((a)[0]), "r"((a)[1]), "r"((a)[2]), "r"((a)[3]), \
                   "r"((b)[0]), "r"((b)[1]))

__device__ __forceinline__ uint32_t f2tf32(float f) {
    uint32_t r;
    asm("cvt.rna.tf32.f32 %0, %1;" : "=r"(r) : "f"(f));
    return r;
}

#define HTILE 16384

template <int ROWS>
__device__ __forceinline__ void load_tileR(
    uint32_t s, const char* gbase, int ldBytes, int tid)
{
    #pragma unroll
    for (int i = 0; i < ROWS / 32; ++i) {
        int id  = tid + 256 * i;
        int row = id >> 3;
        int c   = (id & 7) * 16;
        CP_ASYNC_16(s + SMEM_SWIZZLE_128B(row * 128 + c),
                    gbase + (size_t)row * ldBytes + c);
    }
}

__device__ __forceinline__ void store2(float* p, float a, float b) {
    *(float2*)p = make_float2(a, b);
}
__device__ __forceinline__ void store2(bf16* p, float a, float b) {
    __nv_bfloat162 h;
    h.x = __float2bfloat16(a);
    h.y = __float2bfloat16(b);
    *(__nv_bfloat162*)p = h;
}

// ===========================================================================
// Fused QKV projection: C = (texth+textl) @ (Wh+Wl)^T + bias, 3-term.
// A: [16384, 256] bf16 hi/lo.  B: [768, 256] bf16 hi/lo (WqT|WkT|WvT).
// Epilogue: n0<512 -> bf16 into qk buffer (ld 512); n0>=512 -> fp32 v (ld 256).
// CTA 128x128, warps 2x4, warp tile 64x32, kIters=4, double buffer.
// ===========================================================================
#define SMEM_QKV (2 * 4 * HTILE + 1024)

__global__ void __launch_bounds__(256)
hmma_qkv(const bf16* __restrict__ Ah, const bf16* __restrict__ Al,
         const bf16* __restrict__ Bh, const bf16* __restrict__ Bl,
         const float* __restrict__ gbias,
         bf16* __restrict__ Cqk, float* __restrict__ Cv)
{
    extern __shared__ char dsm[];
    const uint32_t base = (smem_u32(dsm) + 1023) & ~1023u;
    constexpr uint32_t OAL = HTILE;
    constexpr uint32_t OBH = 2u * HTILE;
    constexpr uint32_t OBL = 3u * HTILE;
    constexpr int TPB = 4;

    const int tid  = threadIdx.x;
    const int lane = tid & 31;
    const int wid  = tid >> 5;
    const int wm0  = (wid & 1) * 64;
    const int wn0  = (wid >> 1) * 32;
    const int lr   = lane & 15;
    const int lc   = lane >> 4;

    const int m0 = blockIdx.y * 128;
    const int n0 = blockIdx.x * 128;
    const char* Ahb = (const char*)(Ah + (size_t)m0 * D_);
    const char* Alb = (const char*)(Al + (size_t)m0 * D_);
    const char* Bhb = (const char*)(Bh + (size_t)n0 * D_);
    const char* Blb = (const char*)(Bl + (size_t)n0 * D_);
    const int ldAB = D_ * 2;

    float acc[4][4][4];
    #pragma unroll
    for (int i = 0; i < 4; ++i)
        #pragma unroll
        for (int j = 0; j < 4; ++j)
            #pragma unroll
            for (int r = 0; r < 4; ++r) acc[i][j][r] = 0.0f;

    load_tileR<128>(base,       Ahb, ldAB, tid);
    load_tileR<128>(base + OAL, Alb, ldAB, tid);
    load_tileR<128>(base + OBH, Bhb, ldAB, tid);
    load_tileR<128>(base + OBL, Blb, ldAB, tid);
    CP_ASYNC_COMMIT();
    CP_ASYNC_WAIT_ALL();
    __syncthreads();

    const int kIters = D_ / 64;   // 4
    for (int kt = 0; kt < kIters; ++kt) {
        const int buf = kt & 1;
        const uint32_t cAh = base + buf * (TPB * HTILE);
        const uint32_t cAl = cAh + OAL;
        const uint32_t cBh = cAh + OBH;
        const uint32_t cBl = cAh + OBL;

        if (kt + 1 < kIters) {
            const uint32_t nx = base + (buf ^ 1) * (TPB * HTILE);
            const size_t ko = (size_t)(kt + 1) * 128;
            load_tileR<128>(nx,       Ahb + ko, ldAB, tid);
            load_tileR<128>(nx + OAL, Alb + ko, ldAB, tid);
            load_tileR<128>(nx + OBH, Bhb + ko, ldAB, tid);
            load_tileR<128>(nx + OBL, Blb + ko, ldAB, tid);
            CP_ASYNC_COMMIT();
        }

        #pragma unroll
        for (int ks = 0; ks < 4; ++ks) {
            uint32_t afh[4][4], afl[4][4];
            uint32_t bfh[4][2], bfl[4][2];
            const int csel = ks * 2 + lc;

            #pragma unroll
            for (int mi = 0; mi < 4; ++mi) {
                const int row = wm0 + mi * 16 + lr;
                const uint32_t so = SMEM_SWIZZLE_128B(row * 128 + csel * 16);
                LDMATRIX_X4(afh[mi][0], afh[mi][1], afh[mi][2], afh[mi][3], cAh + so);
                LDMATRIX_X4(afl[mi][0], afl[mi][1], afl[mi][2], afl[mi][3], cAl + so);
            }
            #pragma unroll
            for (int nb = 0; nb < 2; ++nb) {
                const int row = wn0 + nb * 16 + lr;
                const uint32_t so = SMEM_SWIZZLE_128B(row * 128 + csel * 16);
                uint32_t r0, r1, r2, r3;
                LDMATRIX_X4(r0, r1, r2, r3, cBh + so);
                bfh[nb * 2][0]     = r0;  bfh[nb * 2][1]     = r2;
                bfh[nb * 2 + 1][0] = r1;  bfh[nb * 2 + 1][1] = r3;
                LDMATRIX_X4(r0, r1, r2, r3, cBl + so);
                bfl[nb * 2][0]     = r0;  bfl[nb * 2][1]     = r2;
                bfl[nb * 2 + 1][0] = r1;  bfl[nb * 2 + 1][1] = r3;
            }

            #pragma unroll
            for (int mi = 0; mi < 4; ++mi)
                #pragma unroll
                for (int nj = 0; nj < 4; ++nj) {
                    MMA_BF16(acc[mi][nj], afh[mi], bfh[nj]);
                    MMA_BF16(acc[mi][nj], afl[mi], bfh[nj]);
                    MMA_BF16(acc[mi][nj], afh[mi], bfl[nj]);
                }
        }

        CP_ASYNC_WAIT_ALL();
        __syncthreads();
    }

    // mixed epilogue
    const int r     = lane >> 2;
    const int cpair = (lane & 3) * 2;
    #pragma unroll
    for (int mi = 0; mi < 4; ++mi) {
        #pragma unroll
        for (int nj = 0; nj < 4; ++nj) {
            const int col = n0 + wn0 + nj * 8 + cpair;     // 0..767
            const float b0 = gbias[col], b1 = gbias[col + 1];
            const int row0 = m0 + wm0 + mi * 16 + r;
            float v0 = acc[mi][nj][0] + b0, v1 = acc[mi][nj][1] + b1;
            float v2 = acc[mi][nj][2] + b0, v3 = acc[mi][nj][3] + b1;
            if (n0 < 512) {
                bf16* p = Cqk + (size_t)row0 * 512 + col;
                store2(p, v0, v1);
                store2(p + (size_t)8 * 512, v2, v3);
            } else {
                float* p = Cv + (size_t)row0 * D_ + (col - 512);
                store2(p, v0, v1);
                store2(p + (size_t)8 * D_, v2, v3);
            }
        }
    }
}

// ===========================================================================
// Generic NT bf16 HMMA GEMM, CTA 128x128 — used for pass 2 (TERMS=1).
// ===========================================================================
template <int TERMS, typename OutT>
__global__ void __launch_bounds__(256, TERMS == 1 ? 2 : 1)
hmma_g(const bf16* __restrict__ Ah, const bf16* __restrict__ Bh,
       OutT* __restrict__ C,
       int kIters, int ldA, int ldB, int ldC,
       long long sA, long long sB, long long sC)
{
    extern __shared__ char dsm[];
    const uint32_t base = (smem_u32(dsm) + 1023) & ~1023u;
    constexpr int TPB = 2;
    constexpr uint32_t OBH = HTILE;

    const int tid  = threadIdx.x;
    const int lane = tid & 31;
    const int wid  = tid >> 5;
    const int wm0  = (wid & 1) * 64;
    const int wn0  = (wid >> 1) * 32;
    const int lr   = lane & 15;
    const int lc   = lane >> 4;

    const int b  = blockIdx.z;
    const int m0 = blockIdx.y * 128;
    const int n0 = blockIdx.x * 128;
    const char* Ahb = (const char*)(Ah + (size_t)b * sA + (size_t)m0 * ldA);
    const char* Bhb = (const char*)(Bh + (size_t)b * sB + (size_t)n0 * ldB);
    const int ldAB = ldA * 2;
    const int ldBB = ldB * 2;

    float acc[4][4][4];
    #pragma unroll
    for (int i = 0; i < 4; ++i)
        #pragma unroll
        for (int j = 0; j < 4; ++j)
            #pragma unroll
            for (int r = 0; r < 4; ++r) acc[i][j][r] = 0.0f;

    load_tileR<128>(base,       Ahb, ldAB, tid);
    load_tileR<128>(base + OBH, Bhb, ldBB, tid);
    CP_ASYNC_COMMIT();
    CP_ASYNC_WAIT_ALL();
    __syncthreads();

    for (int kt = 0; kt < kIters; ++kt) {
        const int buf = kt & 1;
        const uint32_t cAh = base + buf * (TPB * HTILE);
        const uint32_t cBh = cAh + OBH;

        if (kt + 1 < kIters) {
            const uint32_t nx = base + (buf ^ 1) * (TPB * HTILE);
            const size_t ko = (size_t)(kt + 1) * 128;
            load_tileR<128>(nx,       Ahb + ko, ldAB, tid);
            load_tileR<128>(nx + OBH, Bhb + ko, ldBB, tid);
            CP_ASYNC_COMMIT();
        }

        #pragma unroll
        for (int ks = 0; ks < 4; ++ks) {
            uint32_t af[4][4];
            uint32_t bfr[4][2];
            const int csel = ks * 2 + lc;

            #pragma unroll
            for (int mi = 0; mi < 4; ++mi) {
                const int row = wm0 + mi * 16 + lr;
                LDMATRIX_X4(af[mi][0], af[mi][1], af[mi][2], af[mi][3],
                            cAh + SMEM_SWIZZLE_128B(row * 128 + csel * 16));
            }
            #pragma unroll
            for (int nb = 0; nb < 2; ++nb) {
                const int row = wn0 + nb * 16 + lr;
                uint32_t r0, r1, r2, r3;
                LDMATRIX_X4(r0, r1, r2, r3,
                            cBh + SMEM_SWIZZLE_128B(row * 128 + csel * 16));
                bfr[nb * 2][0]     = r0;  bfr[nb * 2][1]     = r2;
                bfr[nb * 2 + 1][0] = r1;  bfr[nb * 2 + 1][1] = r3;
            }

            #pragma unroll
            for (int mi = 0; mi < 4; ++mi)
                #pragma unroll
                for (int nj = 0; nj < 4; ++nj)
                    MMA_BF16(acc[mi][nj], af[mi], bfr[nj]);
        }

        CP_ASYNC_WAIT_ALL();
        __syncthreads();
    }

    const size_t crow = (size_t)b * sC + (size_t)(m0 + wm0) * ldC + n0 + wn0;
    const int r     = lane >> 2;
    const int cpair = (lane & 3) * 2;
    #pragma unroll
    for (int mi = 0; mi < 4; ++mi) {
        #pragma unroll
        for (int nj = 0; nj < 4; ++nj) {
            const size_t off0 = crow + (size_t)(mi * 16 + r) * ldC + nj * 8 + cpair;
            store2(C + off0, acc[mi][nj][0], acc[mi][nj][1]);
            store2(C + off0 + (size_t)8 * ldC, acc[mi][nj][2], acc[mi][nj][3]);
        }
    }
}

// ===========================================================================
// Pass 4: bf16 HMMA, CTA 128x256, 3-stage pipeline (R8)
// ===========================================================================
#define P4_AT 16384
#define P4_BT 32768
#define P4_BUF (P4_AT + P4_BT)
#define SMEM_P4 (3 * P4_BUF + 1024)

__global__ void __launch_bounds__(256)
hmma_p4(const bf16* __restrict__ A, const bf16* __restrict__ Bt,
        float* __restrict__ C)
{
    extern __shared__ char dsm[];
    const uint32_t base = (smem_u32(dsm) + 1023) & ~1023u;

    const int tid  = threadIdx.x;
    const int lane = tid & 31;
    const int wid  = tid >> 5;
    const int wm0  = (wid & 1) * 64;
    const int wn0  = (wid >> 1) * 64;
    const int lr   = lane & 15;
    const int lc   = lane >> 4;

    const int b  = blockIdx.z;
    const int m0 = blockIdx.y * 128;
    const int n0 = blockIdx.x * 256;
    const char* Ab = (const char*)(A  + ((size_t)b * N_ + m0) * N_);
    const char* Bb = (const char*)(Bt + ((size_t)b * N_ + n0) * N_);
    const int ld = N_ * 2;

    float acc[4][8][4];
    #pragma unroll
    for (int i = 0; i < 4; ++i)
        #pragma unroll
        for (int j = 0; j < 8; ++j)
            #pragma unroll
            for (int r = 0; r < 4; ++r) acc[i][j][r] = 0.0f;

    const int KITER = N_ / 64;

    load_tileR<128>(base,         Ab, ld, tid);
    load_tileR<256>(base + P4_AT, Bb, ld, tid);
    CP_ASYNC_COMMIT();
    load_tileR<128>(base + P4_BUF,         Ab + 128, ld, tid);
    load_tileR<256>(base + P4_BUF + P4_AT, Bb + 128, ld, tid);
    CP_ASYNC_COMMIT();

    for (int kt = 0; kt < KITER; ++kt) {
        if (kt + 1 < KITER) { CP_ASYNC_WAIT_1(); } else { CP_ASYNC_WAIT_ALL(); }
        __syncthreads();

        if (kt + 2 < KITER) {
            const uint32_t nx = base + ((kt + 2) % 3) * P4_BUF;
            const size_t ko = (size_t)(kt + 2) * 128;
            load_tileR<128>(nx,         Ab + ko, ld, tid);
            load_tileR<256>(nx + P4_AT, Bb + ko, ld, tid);
            CP_ASYNC_COMMIT();
        }

        const uint32_t cA = base + (kt % 3) * P4_BUF;
        const uint32_t cB = cA + P4_AT;

        #pragma unroll
        for (int ks = 0; ks < 4; ++ks) {
            uint32_t af[4][4];
            uint32_t bfr[8][2];
            const int csel = ks * 2 + lc;

            #pragma unroll
            for (int mi = 0; mi < 4; ++mi) {
                const int row = wm0 + mi * 16 + lr;
                LDMATRIX_X4(af[mi][0], af[mi][1], af[mi][2], af[mi][3],
                            cA + SMEM_SWIZZLE_128B(row * 128 + csel * 16));
            }
            #pragma unroll
            for (int nb = 0; nb < 4; ++nb) {
                const int row = wn0 + nb * 16 + lr;
                uint32_t r0, r1, r2, r3;
                LDMATRIX_X4(r0, r1, r2, r3,
                            cB + SMEM_SWIZZLE_128B(row * 128 + csel * 16));
                bfr[nb * 2][0]     = r0;  bfr[nb * 2][1]     = r2;
                bfr[nb * 2 + 1][0] = r1;  bfr[nb * 2 + 1][1] = r3;
            }

            #pragma unroll
            for (int mi = 0; mi < 4; ++mi)
                #pragma unroll
                for (int nj = 0; nj < 8; ++nj)
                    MMA_BF16(acc[mi][nj], af[mi], bfr[nj]);
        }
    }

    const size_t crow = ((size_t)b * N_ + m0 + wm0) * N_ + n0 + wn0;
    const int r     = lane >> 2;
    const int cpair = (lane & 3) * 2;
    #pragma unroll
    for (int mi = 0; mi < 4; ++mi) {
        #pragma unroll
        for (int nj = 0; nj < 8; ++nj) {
            const size_t off0 = crow + (size_t)(mi * 16 + r) * N_ + nj * 8 + cpair;
            *(float2*)(C + off0) = make_float2(acc[mi][nj][0], acc[mi][nj][1]);
            *(float2*)(C + off0 + (size_t)8 * N_) =
                make_float2(acc[mi][nj][2], acc[mi][nj][3]);
        }
    }
}

// ===========================================================================
// Pass 5: tf32 mma (R8)
// ===========================================================================
#define P5T_STRIDE 68
#define P5T_TILE  (128 * P5T_STRIDE * 4)
#define P5T_BUF   (2 * P5T_TILE)
#define SMEM_P5T  (2 * P5T_BUF + 1024)

__global__ void __launch_bounds__(256)
tmma_out(const float* __restrict__ A,
         const float* __restrict__ Bt,
         float* __restrict__ C)
{
    extern __shared__ char dsm[];
    const uint32_t base = (smem_u32(dsm) + 1023) & ~1023u;
    char* dbase = dsm + (base - smem_u32(dsm));

    const int tid  = threadIdx.x;
    const int lane = tid & 31;
    const int wid  = tid >> 5;
    const int wm0  = (wid & 1) * 64;
    const int wn0  = (wid >> 1) * 32;
    const int lg   = lane >> 2;
    const int lt   = lane & 3;

    const int b  = blockIdx.z;
    const int m0 = blockIdx.y * 128;
    const int n0 = blockIdx.x * 128;
    const char* Ab  = (const char*)(A  + ((size_t)b * N_ + m0) * N_);
    const char* Bb  = (const char*)(Bt + ((size_t)b * D_ + n0) * N_);
    const int ldAB = N_ * 4;

    float4 ar[8];

    auto ldg_A = [&](int kt) {
        #pragma unroll
        for (int i = 0; i < 8; ++i) {
            const int id  = tid + 256 * i;
            const int row = id >> 4;
            const int c16 = id & 15;
            ar[i] = *(const float4*)(Ab + (size_t)row * ldAB
                                        + (size_t)kt * 256 + c16 * 16);
        }
    };
    auto sts_A = [&](int buf) {
        uint32_t* sA = (uint32_t*)(dbase + buf * P5T_BUF);
        #pragma unroll
        for (int i = 0; i < 8; ++i) {
            const int id  = tid + 256 * i;
            const int row = id >> 4;
            const int c16 = id & 15;
            uint4 t;
            t.x = f2tf32(ar[i].x);
            t.y = f2tf32(ar[i].y);
            t.z = f2tf32(ar[i].z);
            t.w = f2tf32(ar[i].w);
            *(uint4*)(sA + row * P5T_STRIDE + c16 * 4) = t;
        }
    };
    auto ldB = [&](int buf, int kt) {
        const uint32_t sB = base + buf * P5T_BUF + P5T_TILE;
        const char* g = Bb + (size_t)kt * 256;
        #pragma unroll
        for (int i = 0; i < 8; ++i) {
            const int id  = tid + 256 * i;
            const int row = id >> 4;
            const int c16 = id & 15;
            CP_ASYNC_16(sB + row * (P5T_STRIDE * 4) + c16 * 16,
                        g + (size_t)row * ldAB + c16 * 16);
        }
    };

    float acc[4][4][4];
    #pragma unroll
    for (int i = 0; i < 4; ++i)
        #pragma unroll
        for (int j = 0; j < 4; ++j)
            #pragma unroll
            for (int r = 0; r < 4; ++r) acc[i][j][r] = 0.0f;

    ldB(0, 0);
    CP_ASYNC_COMMIT();
    ldg_A(0);
    sts_A(0);
    CP_ASYNC_WAIT_ALL();
    __syncthreads();

    const int KITER = N_ / 64;
    for (int kt = 0; kt < KITER; ++kt) {
        const int buf = kt & 1;
        const uint32_t* sA = (const uint32_t*)(dbase + buf * P5T_BUF);
        const float*    sB = (const float*)(dbase + buf * P5T_BUF + P5T_TILE);

        if (kt + 1 < KITER) {
            ldB(buf ^ 1, kt + 1);
            CP_ASYNC_COMMIT();
            ldg_A(kt + 1);
        }

        #pragma unroll
        for (int s = 0; s < 8; ++s) {
            const int k0 = s * 8;
            uint32_t af[4][4];
            uint32_t bf[4][2];

            #pragma unroll
            for (int mi = 0; mi < 4; ++mi) {
                const int rb = (wm0 + mi * 16 + lg) * P5T_STRIDE + k0 + lt;
                af[mi][0] = sA[rb];
                af[mi][1] = sA[rb + 8 * P5T_STRIDE];
                af[mi][2] = sA[rb + 4];
                af[mi][3] = sA[rb + 8 * P5T_STRIDE + 4];
            }
            #pragma unroll
            for (int nj = 0; nj < 4; ++nj) {
                const int rb = (wn0 + nj * 8 + lg) * P5T_STRIDE + k0 + lt;
                bf[nj][0] = f2tf32(sB[rb]);
                bf[nj][1] = f2tf32(sB[rb + 4]);
            }

            #pragma unroll
            for (int mi = 0; mi < 4; ++mi)
                #pragma unroll
                for (int nj = 0; nj < 4; ++nj)
                    MMA_TF32(acc[mi][nj], af[mi], bf[nj]);
        }

        if (kt + 1 < KITER) {
            __syncthreads();
            sts_A(buf ^ 1);
            CP_ASYNC_WAIT_ALL();
            __syncthreads();
        }
    }

    float* Cb = C + ((size_t)b * N_ + m0 + wm0) * D_ + n0 + wn0;
    const int cpair = lt * 2;
    #pragma unroll
    for (int mi = 0; mi < 4; ++mi) {
        #pragma unroll
        for (int nj = 0; nj < 4; ++nj) {
            float* p = Cb + (size_t)(mi * 16 + lg) * D_ + nj * 8 + cpair;
            *(float2*)p            = make_float2(acc[mi][nj][0], acc[mi][nj][1]);
            *(float2*)(p + 8 * D_) = make_float2(acc[mi][nj][2], acc[mi][nj][3]);
        }
    }
}

// ===========================================================================
// small kernels
// ===========================================================================
__global__ __launch_bounds__(256)
void split_f32(const float* __restrict__ X, bf16* __restrict__ H,
               bf16* __restrict__ L, size_t n4)
{
    size_t i = (size_t)blockIdx.x * blockDim.x + threadIdx.x;
    if (i >= n4) return;
    float4 v = ((const float4*)X)[i];
    float f[4] = {v.x, v.y, v.z, v.w};
    __nv_bfloat162 hh[2], ll[2];
    #pragma unroll
    for (int j = 0; j < 2; ++j) {
        bf16 h0 = __float2bfloat16(f[2 * j]);
        bf16 h1 = __float2bfloat16(f[2 * j + 1]);
        hh[j].x = h0; hh[j].y = h1;
        ll[j].x = __float2bfloat16(f[2 * j]     - __bfloat162float(h0));
        ll[j].y = __float2bfloat16(f[2 * j + 1] - __bfloat162float(h1));
    }
    ((uint2*)H)[i] = *(uint2*)hh;
    ((uint2*)L)[i] = *(uint2*)ll;
}

// W^T hi/lo for 3 weights + bias concat (grid.z selects matrix)
__global__ __launch_bounds__(256)
void wtrans_split3(const float* __restrict__ W0, const float* __restrict__ W1,
                   const float* __restrict__ W2,
                   const float* __restrict__ b0, const float* __restrict__ b1,
                   const float* __restrict__ b2,
                   bf16* __restrict__ Th, bf16* __restrict__ Tl,
                   float* __restrict__ gbias)
{
    __shared__ float t[32][33];
    const int z = blockIdx.z;
    const float* W = (z == 0) ? W0 : (z == 1) ? W1 : W2;
    const float* bz = (z == 0) ? b0 : (z == 1) ? b1 : b2;
    bf16* Thz = Th + z * D_ * D_;
    bf16* Tlz = Tl + z * D_ * D_;
    if (blockIdx.x == 0 && blockIdx.y == 0)
        gbias[z * D_ + threadIdx.x] = bz[threadIdx.x];
    const int x0 = blockIdx.x * 32;
    const int y0 = blockIdx.y * 32;
    const int tx = threadIdx.x & 31;
    const int ty = threadIdx.x >> 5;
    #pragma unroll
    for (int j = 0; j < 4; ++j)
        t[ty + 8 * j][tx] = W[(y0 + ty + 8 * j) * D_ + x0 + tx];
    __syncthreads();
    #pragma unroll
    for (int j = 0; j < 4; ++j) {
        float val = t[tx][ty + 8 * j];
        bf16 hi = __float2bfloat16(val);
        const int off = (x0 + ty + 8 * j) * D_ + y0 + tx;
        Thz[off] = hi;
        Tlz[off] = __float2bfloat16(val - __bfloat162float(hi));
    }
}

__global__ __launch_bounds__(256)
void softmax_warp(const bf16* __restrict__ S, bf16* __restrict__ O, float scale)
{
    const int lane = threadIdx.x & 31;
    const int w    = threadIdx.x >> 5;
    const size_t row = (size_t)blockIdx.x * 8 + w;
    const uint4* p = (const uint4*)(S + row * N_);
    uint4* o       = (uint4*)(O + row * N_);

    float vals[64];
    float m = -1e30f;
    #pragma unroll
    for (int c = 0; c < 8; ++c) {
        uint4 raw = p[c * 32 + lane];
        __nv_bfloat162* pr = (__nv_bfloat162*)&raw;
        #pragma unroll
        for (int i = 0; i < 4; ++i) {
            float2 f = __bfloat1622float2(pr[i]);
            vals[c * 8 + 2 * i]     = f.x * scale;
            vals[c * 8 + 2 * i + 1] = f.y * scale;
            m = fmaxf(m, fmaxf(f.x * scale, f.y * scale));
        }
    }
    #pragma unroll
    for (int s = 16; s > 0; s >>= 1)
        m = fmaxf(m, __shfl_xor_sync(0xFFFFFFFFu, m, s));

    float sum = 0.0f;
    #pragma unroll
    for (int i = 0; i < 64; ++i) {
        vals[i] = __expf(vals[i] - m);
        sum += vals[i];
    }
    #pragma unroll
    for (int s = 16; s > 0; s >>= 1)
        sum += __shfl_xor_sync(0xFFFFFFFFu, sum, s);
    const float inv = 1.0f / sum;

    #pragma unroll
    for (int c = 0; c < 8; ++c) {
        uint4 outv;
        __nv_bfloat162* po = (__nv_bfloat162*)&outv;
        #pragma unroll
        for (int i = 0; i < 4; ++i) {
            po[i].x = __float2bfloat16(vals[c * 8 + 2 * i] * inv);
            po[i].y = __float2bfloat16(vals[c * 8 + 2 * i + 1] * inv);
        }
        o[c * 32 + lane] = outv;
    }
}

__global__ __launch_bounds__(256)
void transpose_bf16(const float* __restrict__ A, bf16* __restrict__ T)
{
    __shared__ float t[32][33];
    const int b  = blockIdx.z;
    const int x0 = blockIdx.x * 32;
    const int y0 = blockIdx.y * 32;
    const float* Ab = A + (size_t)b * N_ * N_;
    bf16* Tb = T + (size_t)b * N_ * N_;
    const int tx = threadIdx.x & 31;
    const int ty = threadIdx.x >> 5;
    #pragma unroll
    for (int j = 0; j < 4; ++j)
        t[ty + 8 * j][tx] = Ab[(size_t)(y0 + ty + 8 * j) * N_ + x0 + tx];
    __syncthreads();
    #pragma unroll
    for (int j = 0; j < 4; ++j)
        Tb[(size_t)(x0 + ty + 8 * j) * N_ + y0 + tx] =
            __float2bfloat16(t[tx][ty + 8 * j]);
}

__global__ __launch_bounds__(256)
void transpose_f32(const float* __restrict__ A, float* __restrict__ T)
{
    __shared__ float t[32][33];
    const int b  = blockIdx.z;
    const int x0 = blockIdx.x * 32;
    const int y0 = blockIdx.y * 32;
    const float* Ab = A + (size_t)b * N_ * D_;
    float* Tb = T + (size_t)b * D_ * N_;
    const int tx = threadIdx.x & 31;
    const int ty = threadIdx.x >> 5;
    #pragma unroll
    for (int j = 0; j < 4; ++j)
        t[ty + 8 * j][tx] = Ab[(size_t)(y0 + ty + 8 * j) * D_ + x0 + tx];
    __syncthreads();
    #pragma unroll
    for (int j = 0; j < 4; ++j)
        Tb[(size_t)(x0 + ty + 8 * j) * N_ + y0 + tx] = t[tx][ty + 8 * j];
}

// ===========================================================================
extern "C" void kernel_launch(void* const* d_in, const int* in_sizes, int n_in,
                              void* d_out, int out_size)
{
    const float* text = (const float*)d_in[0];
    const float* adj  = (const float*)d_in[1];
    const float* Wq   = (const float*)d_in[2];
    const float* bq   = (const float*)d_in[3];
    const float* Wk   = (const float*)d_in[4];
    const float* bk   = (const float*)d_in[5];
    const float* Wv   = (const float*)d_in[6];
    const float* bv   = (const float*)d_in[7];

    float* out     = (float*)d_out;
    float* new_adj = out + (long long)B_ * N_ * D_;

    bf16 *pth, *ptl, *pwth, *pwtl, *pqk, *pattn, *padjT;
    float *pv, *pvt, *ps, *pbias;
    cudaGetSymbolAddress((void**)&pth,  g_texth);
    cudaGetSymbolAddress((void**)&ptl,  g_textl);
    cudaGetSymbolAddress((void**)&pwth, g_wth);
    cudaGetSymbolAddress((void**)&pwtl, g_wtl);
    cudaGetSymbolAddress((void**)&pbias, g_bias);
    cudaGetSymbolAddress((void**)&pqk,  g_qkb);
    cudaGetSymbolAddress((void**)&pv,   g_v);
    cudaGetSymbolAddress((void**)&pvt,  g_vt);
    cudaGetSymbolAddress((void**)&ps,   g_s);
    cudaGetSymbolAddress((void**)&pattn, g_attn);
    cudaGetSymbolAddress((void**)&padjT, g_adjT);

    bf16* psb = (bf16*)ps;

    const int SMEM_G1 = 2 * 2 * HTILE + 1024;
    cudaFuncSetAttribute((const void*)hmma_g<1, bf16>,
                         cudaFuncAttributeMaxDynamicSharedMemorySize, SMEM_G1);
    cudaFuncSetAttribute((const void*)hmma_qkv,
                         cudaFuncAttributeMaxDynamicSharedMemorySize, SMEM_QKV);
    cudaFuncSetAttribute((const void*)hmma_p4,
                         cudaFuncAttributeMaxDynamicSharedMemorySize, SMEM_P4);
    cudaFuncSetAttribute((const void*)tmma_out,
                         cudaFuncAttributeMaxDynamicSharedMemorySize, SMEM_P5T);

    const dim3 t(256);
    const long long sQK = (long long)N_ * 512;
    const long long sS  = (long long)N_ * N_;

    // pre: split text; transpose+split weights + bias concat
    {
        const size_t n4 = (size_t)B_ * N_ * D_ / 4;
        split_f32<<<(unsigned)((n4 + 255) / 256), t>>>(text, pth, ptl, n4);
        dim3 g(D_ / 32, D_ / 32, 3);
        wtrans_split3<<<g, t>>>(Wq, Wk, Wv, bq, bk, bv, pwth, pwtl, pbias);
    }

    // adjT (independent)
    {
        dim3 g(N_ / 32, N_ / 32, B_);
        transpose_bf16<<<g, t>>>(adj, padjT);
    }

    // pass 1: fused q|k|v projection (N=768, one launch)
    {
        dim3 g(768 / 128, (B_ * N_) / 128, 1);   // (6, 128, 1)
        hmma_qkv<<<g, t, SMEM_QKV>>>(pth, ptl, pwth, pwtl, pbias, pqk, pv);
    }

    // v^T fp32
    {
        dim3 g(D_ / 32, N_ / 32, B_);
        transpose_f32<<<g, t>>>(pv, pvt);
    }

    // pass 2: S = q @ k^T -> bf16
    {
        dim3 g(N_ / 128, N_ / 128, B_);
        hmma_g<1, bf16><<<g, t, SMEM_G1>>>(
            pqk, pqk + 256, psb, D_ / 64, 512, 512, N_, sQK, sQK, sS);
    }

    // pass 3: softmax (warp per row)
    softmax_warp<<<B_ * N_ / 8, t>>>(psb, pattn, 1.0f / 16.0f);

    // pass 4: new_adj = attn @ adjT^T
    {
        dim3 g(N_ / 256, N_ / 128, B_);
        hmma_p4<<<g, t, SMEM_P4>>>(pattn, padjT, new_adj);
    }

    // pass 5: out = new_adj @ vT^T  (tf32)
    {
        dim3 g(D_ / 128, N_ / 128, B_);
        tmma_out<<<g, t, SMEM_P5T>>>(new_adj, pvt, out);
    }
}

// round 12
// speedup vs baseline: 1.0204x; 1.0165x over previous
#include <cuda_runtime.h>
#include <cuda_bf16.h>
#include <cstdint>

// ---------------------------------------------------------------------------
// AttentionGNN Round 11 = R10 with conditional term-count in fused QKV:
//   n0 <  512 (q,k cols): 2-term (Ah@Bh + Al@Bh), skip Bl loads
//   n0 >= 512 (v cols):   3-term (+ Ah@Bl)
// Restores R8's exact accumulation order (rel_err checksum 3.044756e-4)
// while keeping the single-launch projection.
// ---------------------------------------------------------------------------

#define B_   8
#define N_   2048
#define D_   256

typedef __nv_bfloat16 bf16;

// Scratch (device globals)
__device__ bf16  g_texth[(size_t)B_ * N_ * D_];
__device__ bf16  g_textl[(size_t)B_ * N_ * D_];
__device__ bf16  g_wth[3 * D_ * D_];            // WqT|WkT|WvT hi (768x256)
__device__ bf16  g_wtl[3 * D_ * D_];
__device__ float g_bias[3 * D_];                // bq|bk|bv
__device__ bf16  g_qkb[(size_t)B_ * N_ * 512];  // q|k per row
__device__ float g_v  [(size_t)B_ * N_ * D_];
__device__ float g_vt [(size_t)B_ * D_ * N_];
__device__ float g_s  [(size_t)B_ * N_ * N_];
__device__ bf16  g_attn[(size_t)B_ * N_ * N_];
__device__ bf16  g_adjT[(size_t)B_ * N_ * N_];

// ===========================================================================
// helpers
// ===========================================================================
__device__ __forceinline__ uint32_t smem_u32(const void* p) {
    uint32_t a;
    asm("{ .reg .u64 t; cvta.to.shared.u64 t, %1; cvt.u32.u64 %0, t; }"
        : "=r"(a) : "l"(p));
    return a;
}

#define SMEM_SWIZZLE_128B(off) ((off) ^ (((off) >> 3) & 0x70))

#define CP_ASYNC_16(dst, src) \
    asm volatile("cp.async.cg.shared.global [%0], [%1], 16;" \
                 :: "r"(dst), "l"(src) : "memory")
#define CP_ASYNC_COMMIT() asm volatile("cp.async.commit_group;" ::: "memory")
#define CP_ASYNC_WAIT_ALL() asm volatile("cp.async.wait_group 0;" ::: "memory")
#define CP_ASYNC_WAIT_1()  asm volatile("cp.async.wait_group 1;" ::: "memory")

#define LDMATRIX_X4(r0, r1, r2, r3, addr) \
    asm volatile("ldmatrix.sync.aligned.m8n8.x4.shared.b16 {%0,%1,%2,%3}, [%4];" \
                 : "=r"(r0), "=r"(r1), "=r"(r2), "=r"(r3) : "r"(addr))

#define MMA_BF16(d, a, b) \
    asm volatile("mma.sync.aligned.m16n8k16.row.col.f32.bf16.bf16.f32 " \
                 "{%0,%1,%2,%3}, {%4,%5,%6,%7}, {%8,%9}, {%0,%1,%2,%3};" \
                 : "+f"((d)[0]), "+f"((d)[1]), "+f"((d)[2]), "+f"((d)[3]) \
                 : "r"((a)[0]), "r"((a)[1]), "r"((a)[2]), "r"((a)[3]), \
                   "r"((b)[0]), "r"((b)[1]))

#define MMA_TF32(d, a, b) \
    asm volatile("mma.sync.aligned.m16n8k8.row.col.f32.tf32.tf32.f32 " \
                 "{%0,%1,%2,%3}, {%4,%5,%6,%7}, {%8,%9}, {%0,%1,%2,%3};" \
                 : "+f"((d)[0]), "+f"((d)[1]), "+f"((d)[2]), "+f"((d)[3]) \
                 : "r"((a)[0]), "r"((a)[1]), "r"((a)[2]), "r"((a)[3]), \
                   "r"((b)[0]), "r"((b)[1]))

__device__ __forceinline__ uint32_t f2tf32(float f) {
    uint32_t r;
    asm("cvt.rna.tf32.f32 %0, %1;" : "=r"(r) : "f"(f));
    return r;
}

#define HTILE 16384

template <int ROWS>
__device__ __forceinline__ void load_tileR(
    uint32_t s, const char* gbase, int ldBytes, int tid)
{
    #pragma unroll
    for (int i = 0; i < ROWS / 32; ++i) {
        int id  = tid + 256 * i;
        int row = id >> 3;
        int c   = (id & 7) * 16;
        CP_ASYNC_16(s + SMEM_SWIZZLE_128B(row * 128 + c),
                    gbase + (size_t)row * ldBytes + c);
    }
}

__device__ __forceinline__ void store2(float* p, float a, float b) {
    *(float2*)p = make_float2(a, b);
}
__device__ __forceinline__ void store2(bf16* p, float a, float b) {
    __nv_bfloat162 h;
    h.x = __float2bfloat16(a);
    h.y = __float2bfloat16(b);
    *(__nv_bfloat162*)p = h;
}

// ===========================================================================
// Fused QKV projection with per-CTA term count:
//   n0<512: C = (Ah+Al)@Bh^T + bias  -> bf16 qk buffer (ld 512)
//   n0>=512: C = (Ah+Al)@(Bh+Bl)^T + bias (3-term) -> fp32 v (ld 256)
// CTA 128x128, warps 2x4, kIters=4, double buffer [Ah,Al,Bh,Bl].
// ===========================================================================
#define SMEM_QKV (2 * 4 * HTILE + 1024)

__global__ void __launch_bounds__(256)
hmma_qkv(const bf16* __restrict__ Ah, const bf16* __restrict__ Al,
         const bf16* __restrict__ Bh, const bf16* __restrict__ Bl,
         const float* __restrict__ gbias,
         bf16* __restrict__ Cqk, float* __restrict__ Cv)
{
    extern __shared__ char dsm[];
    const uint32_t base = (smem_u32(dsm) + 1023) & ~1023u;
    constexpr uint32_t OAL = HTILE;
    constexpr uint32_t OBH = 2u * HTILE;
    constexpr uint32_t OBL = 3u * HTILE;
    constexpr int TPB = 4;

    const int tid  = threadIdx.x;
    const int lane = tid & 31;
    const int wid  = tid >> 5;
    const int wm0  = (wid & 1) * 64;
    const int wn0  = (wid >> 1) * 32;
    const int lr   = lane & 15;
    const int lc   = lane >> 4;

    const int m0 = blockIdx.y * 128;
    const int n0 = blockIdx.x * 128;
    const bool isV = (n0 >= 512);              // 3-term only for v columns
    const char* Ahb = (const char*)(Ah + (size_t)m0 * D_);
    const char* Alb = (const char*)(Al + (size_t)m0 * D_);
    const char* Bhb = (const char*)(Bh + (size_t)n0 * D_);
    const char* Blb = (const char*)(Bl + (size_t)n0 * D_);
    const int ldAB = D_ * 2;

    float acc[4][4][4];
    #pragma unroll
    for (int i = 0; i < 4; ++i)
        #pragma unroll
        for (int j = 0; j < 4; ++j)
            #pragma unroll
            for (int r = 0; r < 4; ++r) acc[i][j][r] = 0.0f;

    load_tileR<128>(base,       Ahb, ldAB, tid);
    load_tileR<128>(base + OAL, Alb, ldAB, tid);
    load_tileR<128>(base + OBH, Bhb, ldAB, tid);
    if (isV) load_tileR<128>(base + OBL, Blb, ldAB, tid);
    CP_ASYNC_COMMIT();
    CP_ASYNC_WAIT_ALL();
    __syncthreads();

    const int kIters = D_ / 64;   // 4
    for (int kt = 0; kt < kIters; ++kt) {
        const int buf = kt & 1;
        const uint32_t cAh = base + buf * (TPB * HTILE);
        const uint32_t cAl = cAh + OAL;
        const uint32_t cBh = cAh + OBH;
        const uint32_t cBl = cAh + OBL;

        if (kt + 1 < kIters) {
            const uint32_t nx = base + (buf ^ 1) * (TPB * HTILE);
            const size_t ko = (size_t)(kt + 1) * 128;
            load_tileR<128>(nx,       Ahb + ko, ldAB, tid);
            load_tileR<128>(nx + OAL, Alb + ko, ldAB, tid);
            load_tileR<128>(nx + OBH, Bhb + ko, ldAB, tid);
            if (isV) load_tileR<128>(nx + OBL, Blb + ko, ldAB, tid);
            CP_ASYNC_COMMIT();
        }

        #pragma unroll
        for (int ks = 0; ks < 4; ++ks) {
            uint32_t afh[4][4], afl[4][4];
            uint32_t bfh[4][2], bfl[4][2];
            const int csel = ks * 2 + lc;

            #pragma unroll
            for (int mi = 0; mi < 4; ++mi) {
                const int row = wm0 + mi * 16 + lr;
                const uint32_t so = SMEM_SWIZZLE_128B(row * 128 + csel * 16);
                LDMATRIX_X4(afh[mi][0], afh[mi][1], afh[mi][2], afh[mi][3], cAh + so);
                LDMATRIX_X4(afl[mi][0], afl[mi][1], afl[mi][2], afl[mi][3], cAl + so);
            }
            #pragma unroll
            for (int nb = 0; nb < 2; ++nb) {
                const int row = wn0 + nb * 16 + lr;
                const uint32_t so = SMEM_SWIZZLE_128B(row * 128 + csel * 16);
                uint32_t r0, r1, r2, r3;
                LDMATRIX_X4(r0, r1, r2, r3, cBh + so);
                bfh[nb * 2][0]     = r0;  bfh[nb * 2][1]     = r2;
                bfh[nb * 2 + 1][0] = r1;  bfh[nb * 2 + 1][1] = r3;
                if (isV) {
                    LDMATRIX_X4(r0, r1, r2, r3, cBl + so);
                    bfl[nb * 2][0]     = r0;  bfl[nb * 2][1]     = r2;
                    bfl[nb * 2 + 1][0] = r1;  bfl[nb * 2 + 1][1] = r3;
                }
            }

            #pragma unroll
            for (int mi = 0; mi < 4; ++mi)
                #pragma unroll
                for (int nj = 0; nj < 4; ++nj) {
                    MMA_BF16(acc[mi][nj], afh[mi], bfh[nj]);
                    MMA_BF16(acc[mi][nj], afl[mi], bfh[nj]);
                }
            if (isV) {
                #pragma unroll
                for (int mi = 0; mi < 4; ++mi)
                    #pragma unroll
                    for (int nj = 0; nj < 4; ++nj)
                        MMA_BF16(acc[mi][nj], afh[mi], bfl[nj]);
            }
        }

        CP_ASYNC_WAIT_ALL();
        __syncthreads();
    }

    // mixed epilogue
    const int r     = lane >> 2;
    const int cpair = (lane & 3) * 2;
    #pragma unroll
    for (int mi = 0; mi < 4; ++mi) {
        #pragma unroll
        for (int nj = 0; nj < 4; ++nj) {
            const int col = n0 + wn0 + nj * 8 + cpair;     // 0..767
            const float b0 = gbias[col], b1 = gbias[col + 1];
            const int row0 = m0 + wm0 + mi * 16 + r;
            float v0 = acc[mi][nj][0] + b0, v1 = acc[mi][nj][1] + b1;
            float v2 = acc[mi][nj][2] + b0, v3 = acc[mi][nj][3] + b1;
            if (!isV) {
                bf16* p = Cqk + (size_t)row0 * 512 + col;
                store2(p, v0, v1);
                store2(p + (size_t)8 * 512, v2, v3);
            } else {
                float* p = Cv + (size_t)row0 * D_ + (col - 512);
                store2(p, v0, v1);
                store2(p + (size_t)8 * D_, v2, v3);
            }
        }
    }
}

// ===========================================================================
// Generic NT bf16 HMMA GEMM, CTA 128x128 — pass 2.
// ===========================================================================
template <int TERMS, typename OutT>
__global__ void __launch_bounds__(256, TERMS == 1 ? 2 : 1)
hmma_g(const bf16* __restrict__ Ah, const bf16* __restrict__ Bh,
       OutT* __restrict__ C,
       int kIters, int ldA, int ldB, int ldC,
       long long sA, long long sB, long long sC)
{
    extern __shared__ char dsm[];
    const uint32_t base = (smem_u32(dsm) + 1023) & ~1023u;
    constexpr int TPB = 2;
    constexpr uint32_t OBH = HTILE;

    const int tid  = threadIdx.x;
    const int lane = tid & 31;
    const int wid  = tid >> 5;
    const int wm0  = (wid & 1) * 64;
    const int wn0  = (wid >> 1) * 32;
    const int lr   = lane & 15;
    const int lc   = lane >> 4;

    const int b  = blockIdx.z;
    const int m0 = blockIdx.y * 128;
    const int n0 = blockIdx.x * 128;
    const char* Ahb = (const char*)(Ah + (size_t)b * sA + (size_t)m0 * ldA);
    const char* Bhb = (const char*)(Bh + (size_t)b * sB + (size_t)n0 * ldB);
    const int ldAB = ldA * 2;
    const int ldBB = ldB * 2;

    float acc[4][4][4];
    #pragma unroll
    for (int i = 0; i < 4; ++i)
        #pragma unroll
        for (int j = 0; j < 4; ++j)
            #pragma unroll
            for (int r = 0; r < 4; ++r) acc[i][j][r] = 0.0f;

    load_tileR<128>(base,       Ahb, ldAB, tid);
    load_tileR<128>(base + OBH, Bhb, ldBB, tid);
    CP_ASYNC_COMMIT();
    CP_ASYNC_WAIT_ALL();
    __syncthreads();

    for (int kt = 0; kt < kIters; ++kt) {
        const int buf = kt & 1;
        const uint32_t cAh = base + buf * (TPB * HTILE);
        const uint32_t cBh = cAh + OBH;

        if (kt + 1 < kIters) {
            const uint32_t nx = base + (buf ^ 1) * (TPB * HTILE);
            const size_t ko = (size_t)(kt + 1) * 128;
            load_tileR<128>(nx,       Ahb + ko, ldAB, tid);
            load_tileR<128>(nx + OBH, Bhb + ko, ldBB, tid);
            CP_ASYNC_COMMIT();
        }

        #pragma unroll
        for (int ks = 0; ks < 4; ++ks) {
            uint32_t af[4][4];
            uint32_t bfr[4][2];
            const int csel = ks * 2 + lc;

            #pragma unroll
            for (int mi = 0; mi < 4; ++mi) {
                const int row = wm0 + mi * 16 + lr;
                LDMATRIX_X4(af[mi][0], af[mi][1], af[mi][2], af[mi][3],
                            cAh + SMEM_SWIZZLE_128B(row * 128 + csel * 16));
            }
            #pragma unroll
            for (int nb = 0; nb < 2; ++nb) {
                const int row = wn0 + nb * 16 + lr;
                uint32_t r0, r1, r2, r3;
                LDMATRIX_X4(r0, r1, r2, r3,
                            cBh + SMEM_SWIZZLE_128B(row * 128 + csel * 16));
                bfr[nb * 2][0]     = r0;  bfr[nb * 2][1]     = r2;
                bfr[nb * 2 + 1][0] = r1;  bfr[nb * 2 + 1][1] = r3;
            }

            #pragma unroll
            for (int mi = 0; mi < 4; ++mi)
                #pragma unroll
                for (int nj = 0; nj < 4; ++nj)
                    MMA_BF16(acc[mi][nj], af[mi], bfr[nj]);
        }

        CP_ASYNC_WAIT_ALL();
        __syncthreads();
    }

    const size_t crow = (size_t)b * sC + (size_t)(m0 + wm0) * ldC + n0 + wn0;
    const int r     = lane >> 2;
    const int cpair = (lane & 3) * 2;
    #pragma unroll
    for (int mi = 0; mi < 4; ++mi) {
        #pragma unroll
        for (int nj = 0; nj < 4; ++nj) {
            const size_t off0 = crow + (size_t)(mi * 16 + r) * ldC + nj * 8 + cpair;
            store2(C + off0, acc[mi][nj][0], acc[mi][nj][1]);
            store2(C + off0 + (size_t)8 * ldC, acc[mi][nj][2], acc[mi][nj][3]);
        }
    }
}

// ===========================================================================
// Pass 4: bf16 HMMA, CTA 128x256, 3-stage pipeline (R8)
// ===========================================================================
#define P4_AT 16384
#define P4_BT 32768
#define P4_BUF (P4_AT + P4_BT)
#define SMEM_P4 (3 * P4_BUF + 1024)

__global__ void __launch_bounds__(256)
hmma_p4(const bf16* __restrict__ A, const bf16* __restrict__ Bt,
        float* __restrict__ C)
{
    extern __shared__ char dsm[];
    const uint32_t base = (smem_u32(dsm) + 1023) & ~1023u;

    const int tid  = threadIdx.x;
    const int lane = tid & 31;
    const int wid  = tid >> 5;
    const int wm0  = (wid & 1) * 64;
    const int wn0  = (wid >> 1) * 64;
    const int lr   = lane & 15;
    const int lc   = lane >> 4;

    const int b  = blockIdx.z;
    const int m0 = blockIdx.y * 128;
    const int n0 = blockIdx.x * 256;
    const char* Ab = (const char*)(A  + ((size_t)b * N_ + m0) * N_);
    const char* Bb = (const char*)(Bt + ((size_t)b * N_ + n0) * N_);
    const int ld = N_ * 2;

    float acc[4][8][4];
    #pragma unroll
    for (int i = 0; i < 4; ++i)
        #pragma unroll
        for (int j = 0; j < 8; ++j)
            #pragma unroll
            for (int r = 0; r < 4; ++r) acc[i][j][r] = 0.0f;

    const int KITER = N_ / 64;

    load_tileR<128>(base,         Ab, ld, tid);
    load_tileR<256>(base + P4_AT, Bb, ld, tid);
    CP_ASYNC_COMMIT();
    load_tileR<128>(base + P4_BUF,         Ab + 128, ld, tid);
    load_tileR<256>(base + P4_BUF + P4_AT, Bb + 128, ld, tid);
    CP_ASYNC_COMMIT();

    for (int kt = 0; kt < KITER; ++kt) {
        if (kt + 1 < KITER) { CP_ASYNC_WAIT_1(); } else { CP_ASYNC_WAIT_ALL(); }
        __syncthreads();

        if (kt + 2 < KITER) {
            const uint32_t nx = base + ((kt + 2) % 3) * P4_BUF;
            const size_t ko = (size_t)(kt + 2) * 128;
            load_tileR<128>(nx,         Ab + ko, ld, tid);
            load_tileR<256>(nx + P4_AT, Bb + ko, ld, tid);
            CP_ASYNC_COMMIT();
        }

        const uint32_t cA = base + (kt % 3) * P4_BUF;
        const uint32_t cB = cA + P4_AT;

        #pragma unroll
        for (int ks = 0; ks < 4; ++ks) {
            uint32_t af[4][4];
            uint32_t bfr[8][2];
            const int csel = ks * 2 + lc;

            #pragma unroll
            for (int mi = 0; mi < 4; ++mi) {
                const int row = wm0 + mi * 16 + lr;
                LDMATRIX_X4(af[mi][0], af[mi][1], af[mi][2], af[mi][3],
                            cA + SMEM_SWIZZLE_128B(row * 128 + csel * 16));
            }
            #pragma unroll
            for (int nb = 0; nb < 4; ++nb) {
                const int row = wn0 + nb * 16 + lr;
                uint32_t r0, r1, r2, r3;
                LDMATRIX_X4(r0, r1, r2, r3,
                            cB + SMEM_SWIZZLE_128B(row * 128 + csel * 16));
                bfr[nb * 2][0]     = r0;  bfr[nb * 2][1]     = r2;
                bfr[nb * 2 + 1][0] = r1;  bfr[nb * 2 + 1][1] = r3;
            }

            #pragma unroll
            for (int mi = 0; mi < 4; ++mi)
                #pragma unroll
                for (int nj = 0; nj < 8; ++nj)
                    MMA_BF16(acc[mi][nj], af[mi], bfr[nj]);
        }
    }

    const size_t crow = ((size_t)b * N_ + m0 + wm0) * N_ + n0 + wn0;
    const int r     = lane >> 2;
    const int cpair = (lane & 3) * 2;
    #pragma unroll
    for (int mi = 0; mi < 4; ++mi) {
        #pragma unroll
        for (int nj = 0; nj < 8; ++nj) {
            const size_t off0 = crow + (size_t)(mi * 16 + r) * N_ + nj * 8 + cpair;
            *(float2*)(C + off0) = make_float2(acc[mi][nj][0], acc[mi][nj][1]);
            *(float2*)(C + off0 + (size_t)8 * N_) =
                make_float2(acc[mi][nj][2], acc[mi][nj][3]);
        }
    }
}

// ===========================================================================
// Pass 5: tf32 mma (R8)
// ===========================================================================
#define P5T_STRIDE 68
#define P5T_TILE  (128 * P5T_STRIDE * 4)
#define P5T_BUF   (2 * P5T_TILE)
#define SMEM_P5T  (2 * P5T_BUF + 1024)

__global__ void __launch_bounds__(256)
tmma_out(const float* __restrict__ A,
         const float* __restrict__ Bt,
         float* __restrict__ C)
{
    extern __shared__ char dsm[];
    const uint32_t base = (smem_u32(dsm) + 1023) & ~1023u;
    char* dbase = dsm + (base - smem_u32(dsm));

    const int tid  = threadIdx.x;
    const int lane = tid & 31;
    const int wid  = tid >> 5;
    const int wm0  = (wid & 1) * 64;
    const int wn0  = (wid >> 1) * 32;
    const int lg   = lane >> 2;
    const int lt   = lane & 3;

    const int b  = blockIdx.z;
    const int m0 = blockIdx.y * 128;
    const int n0 = blockIdx.x * 128;
    const char* Ab  = (const char*)(A  + ((size_t)b * N_ + m0) * N_);
    const char* Bb  = (const char*)(Bt + ((size_t)b * D_ + n0) * N_);
    const int ldAB = N_ * 4;

    float4 ar[8];

    auto ldg_A = [&](int kt) {
        #pragma unroll
        for (int i = 0; i < 8; ++i) {
            const int id  = tid + 256 * i;
            const int row = id >> 4;
            const int c16 = id & 15;
            ar[i] = *(const float4*)(Ab + (size_t)row * ldAB
                                        + (size_t)kt * 256 + c16 * 16);
        }
    };
    auto sts_A = [&](int buf) {
        uint32_t* sA = (uint32_t*)(dbase + buf * P5T_BUF);
        #pragma unroll
        for (int i = 0; i < 8; ++i) {
            const int id  = tid + 256 * i;
            const int row = id >> 4;
            const int c16 = id & 15;
            uint4 t;
            t.x = f2tf32(ar[i].x);
            t.y = f2tf32(ar[i].y);
            t.z = f2tf32(ar[i].z);
            t.w = f2tf32(ar[i].w);
            *(uint4*)(sA + row * P5T_STRIDE + c16 * 4) = t;
        }
    };
    auto ldB = [&](int buf, int kt) {
        const uint32_t sB = base + buf * P5T_BUF + P5T_TILE;
        const char* g = Bb + (size_t)kt * 256;
        #pragma unroll
        for (int i = 0; i < 8; ++i) {
            const int id  = tid + 256 * i;
            const int row = id >> 4;
            const int c16 = id & 15;
            CP_ASYNC_16(sB + row * (P5T_STRIDE * 4) + c16 * 16,
                        g + (size_t)row * ldAB + c16 * 16);
        }
    };

    float acc[4][4][4];
    #pragma unroll
    for (int i = 0; i < 4; ++i)
        #pragma unroll
        for (int j = 0; j < 4; ++j)
            #pragma unroll
            for (int r = 0; r < 4; ++r) acc[i][j][r] = 0.0f;

    ldB(0, 0);
    CP_ASYNC_COMMIT();
    ldg_A(0);
    sts_A(0);
    CP_ASYNC_WAIT_ALL();
    __syncthreads();

    const int KITER = N_ / 64;
    for (int kt = 0; kt < KITER; ++kt) {
        const int buf = kt & 1;
        const uint32_t* sA = (const uint32_t*)(dbase + buf * P5T_BUF);
        const float*    sB = (const float*)(dbase + buf * P5T_BUF + P5T_TILE);

        if (kt + 1 < KITER) {
            ldB(buf ^ 1, kt + 1);
            CP_ASYNC_COMMIT();
            ldg_A(kt + 1);
        }

        #pragma unroll
        for (int s = 0; s < 8; ++s) {
            const int k0 = s * 8;
            uint32_t af[4][4];
            uint32_t bf[4][2];

            #pragma unroll
            for (int mi = 0; mi < 4; ++mi) {
                const int rb = (wm0 + mi * 16 + lg) * P5T_STRIDE + k0 + lt;
                af[mi][0] = sA[rb];
                af[mi][1] = sA[rb + 8 * P5T_STRIDE];
                af[mi][2] = sA[rb + 4];
                af[mi][3] = sA[rb + 8 * P5T_STRIDE + 4];
            }
            #pragma unroll
            for (int nj = 0; nj < 4; ++nj) {
                const int rb = (wn0 + nj * 8 + lg) * P5T_STRIDE + k0 + lt;
                bf[nj][0] = f2tf32(sB[rb]);
                bf[nj][1] = f2tf32(sB[rb + 4]);
            }

            #pragma unroll
            for (int mi = 0; mi < 4; ++mi)
                #pragma unroll
                for (int nj = 0; nj < 4; ++nj)
                    MMA_TF32(acc[mi][nj], af[mi], bf[nj]);
        }

        if (kt + 1 < KITER) {
            __syncthreads();
            sts_A(buf ^ 1);
            CP_ASYNC_WAIT_ALL();
            __syncthreads();
        }
    }

    float* Cb = C + ((size_t)b * N_ + m0 + wm0) * D_ + n0 + wn0;
    const int cpair = lt * 2;
    #pragma unroll
    for (int mi = 0; mi < 4; ++mi) {
        #pragma unroll
        for (int nj = 0; nj < 4; ++nj) {
            float* p = Cb + (size_t)(mi * 16 + lg) * D_ + nj * 8 + cpair;
            *(float2*)p            = make_float2(acc[mi][nj][0], acc[mi][nj][1]);
            *(float2*)(p + 8 * D_) = make_float2(acc[mi][nj][2], acc[mi][nj][3]);
        }
    }
}

// ===========================================================================
// small kernels
// ===========================================================================
__global__ __launch_bounds__(256)
void split_f32(const float* __restrict__ X, bf16* __restrict__ H,
               bf16* __restrict__ L, size_t n4)
{
    size_t i = (size_t)blockIdx.x * blockDim.x + threadIdx.x;
    if (i >= n4) return;
    float4 v = ((const float4*)X)[i];
    float f[4] = {v.x, v.y, v.z, v.w};
    __nv_bfloat162 hh[2], ll[2];
    #pragma unroll
    for (int j = 0; j < 2; ++j) {
        bf16 h0 = __float2bfloat16(f[2 * j]);
        bf16 h1 = __float2bfloat16(f[2 * j + 1]);
        hh[j].x = h0; hh[j].y = h1;
        ll[j].x = __float2bfloat16(f[2 * j]     - __bfloat162float(h0));
        ll[j].y = __float2bfloat16(f[2 * j + 1] - __bfloat162float(h1));
    }
    ((uint2*)H)[i] = *(uint2*)hh;
    ((uint2*)L)[i] = *(uint2*)ll;
}

__global__ __launch_bounds__(256)
void wtrans_split3(const float* __restrict__ W0, const float* __restrict__ W1,
                   const float* __restrict__ W2,
                   const float* __restrict__ b0, const float* __restrict__ b1,
                   const float* __restrict__ b2,
                   bf16* __restrict__ Th, bf16* __restrict__ Tl,
                   float* __restrict__ gbias)
{
    __shared__ float t[32][33];
    const int z = blockIdx.z;
    const float* W = (z == 0) ? W0 : (z == 1) ? W1 : W2;
    const float* bz = (z == 0) ? b0 : (z == 1) ? b1 : b2;
    bf16* Thz = Th + z * D_ * D_;
    bf16* Tlz = Tl + z * D_ * D_;
    if (blockIdx.x == 0 && blockIdx.y == 0)
        gbias[z * D_ + threadIdx.x] = bz[threadIdx.x];
    const int x0 = blockIdx.x * 32;
    const int y0 = blockIdx.y * 32;
    const int tx = threadIdx.x & 31;
    const int ty = threadIdx.x >> 5;
    #pragma unroll
    for (int j = 0; j < 4; ++j)
        t[ty + 8 * j][tx] = W[(y0 + ty + 8 * j) * D_ + x0 + tx];
    __syncthreads();
    #pragma unroll
    for (int j = 0; j < 4; ++j) {
        float val = t[tx][ty + 8 * j];
        bf16 hi = __float2bfloat16(val);
        const int off = (x0 + ty + 8 * j) * D_ + y0 + tx;
        Thz[off] = hi;
        Tlz[off] = __float2bfloat16(val - __bfloat162float(hi));
    }
}

__global__ __launch_bounds__(256)
void softmax_warp(const bf16* __restrict__ S, bf16* __restrict__ O, float scale)
{
    const int lane = threadIdx.x & 31;
    const int w    = threadIdx.x >> 5;
    const size_t row = (size_t)blockIdx.x * 8 + w;
    const uint4* p = (const uint4*)(S + row * N_);
    uint4* o       = (uint4*)(O + row * N_);

    float vals[64];
    float m = -1e30f;
    #pragma unroll
    for (int c = 0; c < 8; ++c) {
        uint4 raw = p[c * 32 + lane];
        __nv_bfloat162* pr = (__nv_bfloat162*)&raw;
        #pragma unroll
        for (int i = 0; i < 4; ++i) {
            float2 f = __bfloat1622float2(pr[i]);
            vals[c * 8 + 2 * i]     = f.x * scale;
            vals[c * 8 + 2 * i + 1] = f.y * scale;
            m = fmaxf(m, fmaxf(f.x * scale, f.y * scale));
        }
    }
    #pragma unroll
    for (int s = 16; s > 0; s >>= 1)
        m = fmaxf(m, __shfl_xor_sync(0xFFFFFFFFu, m, s));

    float sum = 0.0f;
    #pragma unroll
    for (int i = 0; i < 64; ++i) {
        vals[i] = __expf(vals[i] - m);
        sum += vals[i];
    }
    #pragma unroll
    for (int s = 16; s > 0; s >>= 1)
        sum += __shfl_xor_sync(0xFFFFFFFFu, sum, s);
    const float inv = 1.0f / sum;

    #pragma unroll
    for (int c = 0; c < 8; ++c) {
        uint4 outv;
        __nv_bfloat162* po = (__nv_bfloat162*)&outv;
        #pragma unroll
        for (int i = 0; i < 4; ++i) {
            po[i].x = __float2bfloat16(vals[c * 8 + 2 * i] * inv);
            po[i].y = __float2bfloat16(vals[c * 8 + 2 * i + 1] * inv);
        }
        o[c * 32 + lane] = outv;
    }
}

__global__ __launch_bounds__(256)
void transpose_bf16(const float* __restrict__ A, bf16* __restrict__ T)
{
    __shared__ float t[32][33];
    const int b  = blockIdx.z;
    const int x0 = blockIdx.x * 32;
    const int y0 = blockIdx.y * 32;
    const float* Ab = A + (size_t)b * N_ * N_;
    bf16* Tb = T + (size_t)b * N_ * N_;
    const int tx = threadIdx.x & 31;
    const int ty = threadIdx.x >> 5;
    #pragma unroll
    for (int j = 0; j < 4; ++j)
        t[ty + 8 * j][tx] = Ab[(size_t)(y0 + ty + 8 * j) * N_ + x0 + tx];
    __syncthreads();
    #pragma unroll
    for (int j = 0; j < 4; ++j)
        Tb[(size_t)(x0 + ty + 8 * j) * N_ + y0 + tx] =
            __float2bfloat16(t[tx][ty + 8 * j]);
}

__global__ __launch_bounds__(256)
void transpose_f32(const float* __restrict__ A, float* __restrict__ T)
{
    __shared__ float t[32][33];
    const int b  = blockIdx.z;
    const int x0 = blockIdx.x * 32;
    const int y0 = blockIdx.y * 32;
    const float* Ab = A + (size_t)b * N_ * D_;
    float* Tb = T + (size_t)b * D_ * N_;
    const int tx = threadIdx.x & 31;
    const int ty = threadIdx.x >> 5;
    #pragma unroll
    for (int j = 0; j < 4; ++j)
        t[ty + 8 * j][tx] = Ab[(size_t)(y0 + ty + 8 * j) * D_ + x0 + tx];
    __syncthreads();
    #pragma unroll
    for (int j = 0; j < 4; ++j)
        Tb[(size_t)(x0 + ty + 8 * j) * N_ + y0 + tx] = t[tx][ty + 8 * j];
}

// ===========================================================================
extern "C" void kernel_launch(void* const* d_in, const int* in_sizes, int n_in,
                              void* d_out, int out_size)
{
    const float* text = (const float*)d_in[0];
    const float* adj  = (const float*)d_in[1];
    const float* Wq   = (const float*)d_in[2];
    const float* bq   = (const float*)d_in[3];
    const float* Wk   = (const float*)d_in[4];
    const float* bk   = (const float*)d_in[5];
    const float* Wv   = (const float*)d_in[6];
    const float* bv   = (const float*)d_in[7];

    float* out     = (float*)d_out;
    float* new_adj = out + (long long)B_ * N_ * D_;

    bf16 *pth, *ptl, *pwth, *pwtl, *pqk, *pattn, *padjT;
    float *pv, *pvt, *ps, *pbias;
    cudaGetSymbolAddress((void**)&pth,  g_texth);
    cudaGetSymbolAddress((void**)&ptl,  g_textl);
    cudaGetSymbolAddress((void**)&pwth, g_wth);
    cudaGetSymbolAddress((void**)&pwtl, g_wtl);
    cudaGetSymbolAddress((void**)&pbias, g_bias);
    cudaGetSymbolAddress((void**)&pqk,  g_qkb);
    cudaGetSymbolAddress((void**)&pv,   g_v);
    cudaGetSymbolAddress((void**)&pvt,  g_vt);
    cudaGetSymbolAddress((void**)&ps,   g_s);
    cudaGetSymbolAddress((void**)&pattn, g_attn);
    cudaGetSymbolAddress((void**)&padjT, g_adjT);

    bf16* psb = (bf16*)ps;

    const int SMEM_G1 = 2 * 2 * HTILE + 1024;
    cudaFuncSetAttribute((const void*)hmma_g<1, bf16>,
                         cudaFuncAttributeMaxDynamicSharedMemorySize, SMEM_G1);
    cudaFuncSetAttribute((const void*)hmma_qkv,
                         cudaFuncAttributeMaxDynamicSharedMemorySize, SMEM_QKV);
    cudaFuncSetAttribute((const void*)hmma_p4,
                         cudaFuncAttributeMaxDynamicSharedMemorySize, SMEM_P4);
    cudaFuncSetAttribute((const void*)tmma_out,
                         cudaFuncAttributeMaxDynamicSharedMemorySize, SMEM_P5T);

    const dim3 t(256);
    const long long sQK = (long long)N_ * 512;
    const long long sS  = (long long)N_ * N_;

    // pre: split text; transpose+split weights + bias concat
    {
        const size_t n4 = (size_t)B_ * N_ * D_ / 4;
        split_f32<<<(unsigned)((n4 + 255) / 256), t>>>(text, pth, ptl, n4);
        dim3 g(D_ / 32, D_ / 32, 3);
        wtrans_split3<<<g, t>>>(Wq, Wk, Wv, bq, bk, bv, pwth, pwtl, pbias);
    }

    // adjT (independent)
    {
        dim3 g(N_ / 32, N_ / 32, B_);
        transpose_bf16<<<g, t>>>(adj, padjT);
    }

    // pass 1: fused q|k|v projection, conditional term count
    {
        dim3 g(768 / 128, (B_ * N_) / 128, 1);   // (6, 128, 1)
        hmma_qkv<<<g, t, SMEM_QKV>>>(pth, ptl, pwth, pwtl, pbias, pqk, pv);
    }

    // v^T fp32
    {
        dim3 g(D_ / 32, N_ / 32, B_);
        transpose_f32<<<g, t>>>(pv, pvt);
    }

    // pass 2: S = q @ k^T -> bf16
    {
        dim3 g(N_ / 128, N_ / 128, B_);
        hmma_g<1, bf16><<<g, t, SMEM_G1>>>(
            pqk, pqk + 256, psb, D_ / 64, 512, 512, N_, sQK, sQK, sS);
    }

    // pass 3: softmax (warp per row)
    softmax_warp<<<B_ * N_ / 8, t>>>(psb, pattn, 1.0f / 16.0f);

    // pass 4: new_adj = attn @ adjT^T
    {
        dim3 g(N_ / 256, N_ / 128, B_);
        hmma_p4<<<g, t, SMEM_P4>>>(pattn, padjT, new_adj);
    }

    // pass 5: out = new_adj @ vT^T  (tf32)
    {
        dim3 g(D_ / 128, N_ / 128, B_);
        tmma_out<<<g, t, SMEM_P5T>>>(new_adj, pvt, out);
    }
}

// round 13
// speedup vs baseline: 1.0225x; 1.0021x over previous
#include <cuda_runtime.h>
#include <cuda_bf16.h>
#include <cstdint>

// ---------------------------------------------------------------------------
// AttentionGNN Round 12 = R11 + vT transpose fused into QKV epilogue:
//   v CTAs stage their 128x128 output tile transposed in smem (stride 132,
//   conflict-free) and write vT [b][d][n] coalesced. transpose_f32 kernel and
//   the g_v intermediate are deleted. Values bit-identical to R11.
// ---------------------------------------------------------------------------

#define B_   8
#define N_   2048
#define D_   256

typedef __nv_bfloat16 bf16;

// Scratch (device globals)
__device__ bf16  g_texth[(size_t)B_ * N_ * D_];
__device__ bf16  g_textl[(size_t)B_ * N_ * D_];
__device__ bf16  g_wth[3 * D_ * D_];            // WqT|WkT|WvT hi (768x256)
__device__ bf16  g_wtl[3 * D_ * D_];
__device__ float g_bias[3 * D_];                // bq|bk|bv
__device__ bf16  g_qkb[(size_t)B_ * N_ * 512];  // q|k per row
__device__ float g_vt [(size_t)B_ * D_ * N_];   // v^T fp32
__device__ float g_s  [(size_t)B_ * N_ * N_];
__device__ bf16  g_attn[(size_t)B_ * N_ * N_];
__device__ bf16  g_adjT[(size_t)B_ * N_ * N_];

// ===========================================================================
// helpers
// ===========================================================================
__device__ __forceinline__ uint32_t smem_u32(const void* p) {
    uint32_t a;
    asm("{ .reg .u64 t; cvta.to.shared.u64 t, %1; cvt.u32.u64 %0, t; }"
        : "=r"(a) : "l"(p));
    return a;
}

#define SMEM_SWIZZLE_128B(off) ((off) ^ (((off) >> 3) & 0x70))

#define CP_ASYNC_16(dst, src) \
    asm volatile("cp.async.cg.shared.global [%0], [%1], 16;" \
                 :: "r"(dst), "l"(src) : "memory")
#define CP_ASYNC_COMMIT() asm volatile("cp.async.commit_group;" ::: "memory")
#define CP_ASYNC_WAIT_ALL() asm volatile("cp.async.wait_group 0;" ::: "memory")
#define CP_ASYNC_WAIT_1()  asm volatile("cp.async.wait_group 1;" ::: "memory")

#define LDMATRIX_X4(r0, r1, r2, r3, addr) \
    asm volatile("ldmatrix.sync.aligned.m8n8.x4.shared.b16 {%0,%1,%2,%3}, [%4];" \
                 : "=r"(r0), "=r"(r1), "=r"(r2), "=r"(r3) : "r"(addr))

#define MMA_BF16(d, a, b) \
    asm volatile("mma.sync.aligned.m16n8k16.row.col.f32.bf16.bf16.f32 " \
                 "{%0,%1,%2,%3}, {%4,%5,%6,%7}, {%8,%9}, {%0,%1,%2,%3};" \
                 : "+f"((d)[0]), "+f"((d)[1]), "+f"((d)[2]), "+f"((d)[3]) \
                 : "r"((a)[0]), "r"((a)[1]), "r"((a)[2]), "r"((a)[3]), \
                   "r"((b)[0]), "r"((b)[1]))

#define MMA_TF32(d, a, b) \
    asm volatile("mma.sync.aligned.m16n8k8.row.col.f32.tf32.tf32.f32 " \
                 "{%0,%1,%2,%3}, {%4,%5,%6,%7}, {%8,%9}, {%0,%1,%2,%3};" \
                 : "+f"((d)[0]), "+f"((d)[1]), "+f"((d)[2]), "+f"((d)[3]) \
                 : "r"((a)[0]), "r"((a)[1]), "r"((a)[2]), "r"((a)[3]), \
                   "r"((b)[0]), "r"((b)[1]))

__device__ __forceinline__ uint32_t f2tf32(float f) {
    uint32_t r;
    asm("cvt.rna.tf32.f32 %0, %1;" : "=r"(r) : "f"(f));
    return r;
}

#define HTILE 16384

template <int ROWS>
__device__ __forceinline__ void load_tileR(
    uint32_t s, const char* gbase, int ldBytes, int tid)
{
    #pragma unroll
    for (int i = 0; i < ROWS / 32; ++i) {
        int id  = tid + 256 * i;
        int row = id >> 3;
        int c   = (id & 7) * 16;
        CP_ASYNC_16(s + SMEM_SWIZZLE_128B(row * 128 + c),
                    gbase + (size_t)row * ldBytes + c);
    }
}

__device__ __forceinline__ void store2(float* p, float a, float b) {
    *(float2*)p = make_float2(a, b);
}
__device__ __forceinline__ void store2(bf16* p, float a, float b) {
    __nv_bfloat162 h;
    h.x = __float2bfloat16(a);
    h.y = __float2bfloat16(b);
    *(__nv_bfloat162*)p = h;
}

// ===========================================================================
// Fused QKV projection:
//   n0<512 (q,k): 2-term -> bf16 qk buffer (ld 512), direct epilogue
//   n0>=512 (v):  3-term -> fp32, staged transposed in smem, written to
//                 vT [b][d][n] fully coalesced (replaces transpose_f32).
// CTA 128x128, warps 2x4, kIters=4, double buffer [Ah,Al,Bh,Bl] (128 KB).
// Transposed staging buffer (128x132 f32 = 67.6 KB) reuses operand smem
// after the final mainloop syncthreads.
// ===========================================================================
#define SMEM_QKV (2 * 4 * HTILE + 1024)
#define VT_S 132

__global__ void __launch_bounds__(256)
hmma_qkv(const bf16* __restrict__ Ah, const bf16* __restrict__ Al,
         const bf16* __restrict__ Bh, const bf16* __restrict__ Bl,
         const float* __restrict__ gbias,
         bf16* __restrict__ Cqk, float* __restrict__ Cvt)
{
    extern __shared__ char dsm[];
    const uint32_t base = (smem_u32(dsm) + 1023) & ~1023u;
    float* stage = (float*)(dsm + (base - smem_u32(dsm)));   // aliases operands
    constexpr uint32_t OAL = HTILE;
    constexpr uint32_t OBH = 2u * HTILE;
    constexpr uint32_t OBL = 3u * HTILE;
    constexpr int TPB = 4;

    const int tid  = threadIdx.x;
    const int lane = tid & 31;
    const int wid  = tid >> 5;
    const int wm0  = (wid & 1) * 64;
    const int wn0  = (wid >> 1) * 32;
    const int lr   = lane & 15;
    const int lc   = lane >> 4;

    const int m0 = blockIdx.y * 128;
    const int n0 = blockIdx.x * 128;
    const bool isV = (n0 >= 512);
    const char* Ahb = (const char*)(Ah + (size_t)m0 * D_);
    const char* Alb = (const char*)(Al + (size_t)m0 * D_);
    const char* Bhb = (const char*)(Bh + (size_t)n0 * D_);
    const char* Blb = (const char*)(Bl + (size_t)n0 * D_);
    const int ldAB = D_ * 2;

    float acc[4][4][4];
    #pragma unroll
    for (int i = 0; i < 4; ++i)
        #pragma unroll
        for (int j = 0; j < 4; ++j)
            #pragma unroll
            for (int r = 0; r < 4; ++r) acc[i][j][r] = 0.0f;

    load_tileR<128>(base,       Ahb, ldAB, tid);
    load_tileR<128>(base + OAL, Alb, ldAB, tid);
    load_tileR<128>(base + OBH, Bhb, ldAB, tid);
    if (isV) load_tileR<128>(base + OBL, Blb, ldAB, tid);
    CP_ASYNC_COMMIT();
    CP_ASYNC_WAIT_ALL();
    __syncthreads();

    const int kIters = D_ / 64;   // 4
    for (int kt = 0; kt < kIters; ++kt) {
        const int buf = kt & 1;
        const uint32_t cAh = base + buf * (TPB * HTILE);
        const uint32_t cAl = cAh + OAL;
        const uint32_t cBh = cAh + OBH;
        const uint32_t cBl = cAh + OBL;

        if (kt + 1 < kIters) {
            const uint32_t nx = base + (buf ^ 1) * (TPB * HTILE);
            const size_t ko = (size_t)(kt + 1) * 128;
            load_tileR<128>(nx,       Ahb + ko, ldAB, tid);
            load_tileR<128>(nx + OAL, Alb + ko, ldAB, tid);
            load_tileR<128>(nx + OBH, Bhb + ko, ldAB, tid);
            if (isV) load_tileR<128>(nx + OBL, Blb + ko, ldAB, tid);
            CP_ASYNC_COMMIT();
        }

        #pragma unroll
        for (int ks = 0; ks < 4; ++ks) {
            uint32_t afh[4][4], afl[4][4];
            uint32_t bfh[4][2], bfl[4][2];
            const int csel = ks * 2 + lc;

            #pragma unroll
            for (int mi = 0; mi < 4; ++mi) {
                const int row = wm0 + mi * 16 + lr;
                const uint32_t so = SMEM_SWIZZLE_128B(row * 128 + csel * 16);
                LDMATRIX_X4(afh[mi][0], afh[mi][1], afh[mi][2], afh[mi][3], cAh + so);
                LDMATRIX_X4(afl[mi][0], afl[mi][1], afl[mi][2], afl[mi][3], cAl + so);
            }
            #pragma unroll
            for (int nb = 0; nb < 2; ++nb) {
                const int row = wn0 + nb * 16 + lr;
                const uint32_t so = SMEM_SWIZZLE_128B(row * 128 + csel * 16);
                uint32_t r0, r1, r2, r3;
                LDMATRIX_X4(r0, r1, r2, r3, cBh + so);
                bfh[nb * 2][0]     = r0;  bfh[nb * 2][1]     = r2;
                bfh[nb * 2 + 1][0] = r1;  bfh[nb * 2 + 1][1] = r3;
                if (isV) {
                    LDMATRIX_X4(r0, r1, r2, r3, cBl + so);
                    bfl[nb * 2][0]     = r0;  bfl[nb * 2][1]     = r2;
                    bfl[nb * 2 + 1][0] = r1;  bfl[nb * 2 + 1][1] = r3;
                }
            }

            #pragma unroll
            for (int mi = 0; mi < 4; ++mi)
                #pragma unroll
                for (int nj = 0; nj < 4; ++nj) {
                    MMA_BF16(acc[mi][nj], afh[mi], bfh[nj]);
                    MMA_BF16(acc[mi][nj], afl[mi], bfh[nj]);
                }
            if (isV) {
                #pragma unroll
                for (int mi = 0; mi < 4; ++mi)
                    #pragma unroll
                    for (int nj = 0; nj < 4; ++nj)
                        MMA_BF16(acc[mi][nj], afh[mi], bfl[nj]);
            }
        }

        CP_ASYNC_WAIT_ALL();
        __syncthreads();
    }

    const int r     = lane >> 2;
    const int cpair = (lane & 3) * 2;

    if (!isV) {
        // q,k: direct bf16 epilogue
        #pragma unroll
        for (int mi = 0; mi < 4; ++mi) {
            #pragma unroll
            for (int nj = 0; nj < 4; ++nj) {
                const int col = n0 + wn0 + nj * 8 + cpair;
                const float b0 = gbias[col], b1 = gbias[col + 1];
                const int row0 = m0 + wm0 + mi * 16 + r;
                bf16* p = Cqk + (size_t)row0 * 512 + col;
                store2(p, acc[mi][nj][0] + b0, acc[mi][nj][1] + b1);
                store2(p + (size_t)8 * 512, acc[mi][nj][2] + b0, acc[mi][nj][3] + b1);
            }
        }
    } else {
        // v: stage transposed [d][n] in smem (stride VT_S), then coalesced STG
        // write bank = (4*(d) + n) % 32 — conflict-free per warp
        #pragma unroll
        for (int mi = 0; mi < 4; ++mi) {
            #pragma unroll
            for (int nj = 0; nj < 4; ++nj) {
                const int col = n0 + wn0 + nj * 8 + cpair;        // 512..767
                const int d   = col - 512 - (n0 - 512) + (n0 - 512); // local d below
                const float b0 = gbias[col], b1 = gbias[col + 1];
                const int dl  = (col - n0);                       // 0..127 local d
                const int rl0 = wm0 + mi * 16 + r;                // local n
                stage[(size_t)dl * VT_S + rl0]             = acc[mi][nj][0] + b0;
                stage[(size_t)(dl + 1) * VT_S + rl0]       = acc[mi][nj][1] + b1;
                stage[(size_t)dl * VT_S + rl0 + 8]         = acc[mi][nj][2] + b0;
                stage[(size_t)(dl + 1) * VT_S + rl0 + 8]   = acc[mi][nj][3] + b1;
            }
        }
        __syncthreads();

        // coalesced out: vt[b][d0+d][nrow0 + n]
        const int bz    = m0 >> 11;            // m0 / 2048
        const int nrow0 = m0 & 2047;
        const int d0    = n0 - 512;            // 0 or 128
        const int nn  = (tid & 31) * 4;        // 0..124
        const int dw  = tid >> 5;              // 0..7
        #pragma unroll
        for (int dd = 0; dd < 16; ++dd) {
            const int d = dw + dd * 8;
            const float* s = stage + (size_t)d * VT_S + nn;
            float4 v4 = make_float4(s[0], s[1], s[2], s[3]);
            *(float4*)(Cvt + ((size_t)bz * D_ + d0 + d) * N_ + nrow0 + nn) = v4;
        }
    }
}

// ===========================================================================
// Generic NT bf16 HMMA GEMM, CTA 128x128 — pass 2.
// ===========================================================================
template <int TERMS, typename OutT>
__global__ void __launch_bounds__(256, TERMS == 1 ? 2 : 1)
hmma_g(const bf16* __restrict__ Ah, const bf16* __restrict__ Bh,
       OutT* __restrict__ C,
       int kIters, int ldA, int ldB, int ldC,
       long long sA, long long sB, long long sC)
{
    extern __shared__ char dsm[];
    const uint32_t base = (smem_u32(dsm) + 1023) & ~1023u;
    constexpr int TPB = 2;
    constexpr uint32_t OBH = HTILE;

    const int tid  = threadIdx.x;
    const int lane = tid & 31;
    const int wid  = tid >> 5;
    const int wm0  = (wid & 1) * 64;
    const int wn0  = (wid >> 1) * 32;
    const int lr   = lane & 15;
    const int lc   = lane >> 4;

    const int b  = blockIdx.z;
    const int m0 = blockIdx.y * 128;
    const int n0 = blockIdx.x * 128;
    const char* Ahb = (const char*)(Ah + (size_t)b * sA + (size_t)m0 * ldA);
    const char* Bhb = (const char*)(Bh + (size_t)b * sB + (size_t)n0 * ldB);
    const int ldAB = ldA * 2;
    const int ldBB = ldB * 2;

    float acc[4][4][4];
    #pragma unroll
    for (int i = 0; i < 4; ++i)
        #pragma unroll
        for (int j = 0; j < 4; ++j)
            #pragma unroll
            for (int r = 0; r < 4; ++r) acc[i][j][r] = 0.0f;

    load_tileR<128>(base,       Ahb, ldAB, tid);
    load_tileR<128>(base + OBH, Bhb, ldBB, tid);
    CP_ASYNC_COMMIT();
    CP_ASYNC_WAIT_ALL();
    __syncthreads();

    for (int kt = 0; kt < kIters; ++kt) {
        const int buf = kt & 1;
        const uint32_t cAh = base + buf * (TPB * HTILE);
        const uint32_t cBh = cAh + OBH;

        if (kt + 1 < kIters) {
            const uint32_t nx = base + (buf ^ 1) * (TPB * HTILE);
            const size_t ko = (size_t)(kt + 1) * 128;
            load_tileR<128>(nx,       Ahb + ko, ldAB, tid);
            load_tileR<128>(nx + OBH, Bhb + ko, ldBB, tid);
            CP_ASYNC_COMMIT();
        }

        #pragma unroll
        for (int ks = 0; ks < 4; ++ks) {
            uint32_t af[4][4];
            uint32_t bfr[4][2];
            const int csel = ks * 2 + lc;

            #pragma unroll
            for (int mi = 0; mi < 4; ++mi) {
                const int row = wm0 + mi * 16 + lr;
                LDMATRIX_X4(af[mi][0], af[mi][1], af[mi][2], af[mi][3],
                            cAh + SMEM_SWIZZLE_128B(row * 128 + csel * 16));
            }
            #pragma unroll
            for (int nb = 0; nb < 2; ++nb) {
                const int row = wn0 + nb * 16 + lr;
                uint32_t r0, r1, r2, r3;
                LDMATRIX_X4(r0, r1, r2, r3,
                            cBh + SMEM_SWIZZLE_128B(row * 128 + csel * 16));
                bfr[nb * 2][0]     = r0;  bfr[nb * 2][1]     = r2;
                bfr[nb * 2 + 1][0] = r1;  bfr[nb * 2 + 1][1] = r3;
            }

            #pragma unroll
            for (int mi = 0; mi < 4; ++mi)
                #pragma unroll
                for (int nj = 0; nj < 4; ++nj)
                    MMA_BF16(acc[mi][nj], af[mi], bfr[nj]);
        }

        CP_ASYNC_WAIT_ALL();
        __syncthreads();
    }

    const size_t crow = (size_t)b * sC + (size_t)(m0 + wm0) * ldC + n0 + wn0;
    const int r     = lane >> 2;
    const int cpair = (lane & 3) * 2;
    #pragma unroll
    for (int mi = 0; mi < 4; ++mi) {
        #pragma unroll
        for (int nj = 0; nj < 4; ++nj) {
            const size_t off0 = crow + (size_t)(mi * 16 + r) * ldC + nj * 8 + cpair;
            store2(C + off0, acc[mi][nj][0], acc[mi][nj][1]);
            store2(C + off0 + (size_t)8 * ldC, acc[mi][nj][2], acc[mi][nj][3]);
        }
    }
}

// ===========================================================================
// Pass 4: bf16 HMMA, CTA 128x256, 3-stage pipeline (R8)
// ===========================================================================
#define P4_AT 16384
#define P4_BT 32768
#define P4_BUF (P4_AT + P4_BT)
#define SMEM_P4 (3 * P4_BUF + 1024)

__global__ void __launch_bounds__(256)
hmma_p4(const bf16* __restrict__ A, const bf16* __restrict__ Bt,
        float* __restrict__ C)
{
    extern __shared__ char dsm[];
    const uint32_t base = (smem_u32(dsm) + 1023) & ~1023u;

    const int tid  = threadIdx.x;
    const int lane = tid & 31;
    const int wid  = tid >> 5;
    const int wm0  = (wid & 1) * 64;
    const int wn0  = (wid >> 1) * 64;
    const int lr   = lane & 15;
    const int lc   = lane >> 4;

    const int b  = blockIdx.z;
    const int m0 = blockIdx.y * 128;
    const int n0 = blockIdx.x * 256;
    const char* Ab = (const char*)(A  + ((size_t)b * N_ + m0) * N_);
    const char* Bb = (const char*)(Bt + ((size_t)b * N_ + n0) * N_);
    const int ld = N_ * 2;

    float acc[4][8][4];
    #pragma unroll
    for (int i = 0; i < 4; ++i)
        #pragma unroll
        for (int j = 0; j < 8; ++j)
            #pragma unroll
            for (int r = 0; r < 4; ++r) acc[i][j][r] = 0.0f;

    const int KITER = N_ / 64;

    load_tileR<128>(base,         Ab, ld, tid);
    load_tileR<256>(base + P4_AT, Bb, ld, tid);
    CP_ASYNC_COMMIT();
    load_tileR<128>(base + P4_BUF,         Ab + 128, ld, tid);
    load_tileR<256>(base + P4_BUF + P4_AT, Bb + 128, ld, tid);
    CP_ASYNC_COMMIT();

    for (int kt = 0; kt < KITER; ++kt) {
        if (kt + 1 < KITER) { CP_ASYNC_WAIT_1(); } else { CP_ASYNC_WAIT_ALL(); }
        __syncthreads();

        if (kt + 2 < KITER) {
            const uint32_t nx = base + ((kt + 2) % 3) * P4_BUF;
            const size_t ko = (size_t)(kt + 2) * 128;
            load_tileR<128>(nx,         Ab + ko, ld, tid);
            load_tileR<256>(nx + P4_AT, Bb + ko, ld, tid);
            CP_ASYNC_COMMIT();
        }

        const uint32_t cA = base + (kt % 3) * P4_BUF;
        const uint32_t cB = cA + P4_AT;

        #pragma unroll
        for (int ks = 0; ks < 4; ++ks) {
            uint32_t af[4][4];
            uint32_t bfr[8][2];
            const int csel = ks * 2 + lc;

            #pragma unroll
            for (int mi = 0; mi < 4; ++mi) {
                const int row = wm0 + mi * 16 + lr;
                LDMATRIX_X4(af[mi][0], af[mi][1], af[mi][2], af[mi][3],
                            cA + SMEM_SWIZZLE_128B(row * 128 + csel * 16));
            }
            #pragma unroll
            for (int nb = 0; nb < 4; ++nb) {
                const int row = wn0 + nb * 16 + lr;
                uint32_t r0, r1, r2, r3;
                LDMATRIX_X4(r0, r1, r2, r3,
                            cB + SMEM_SWIZZLE_128B(row * 128 + csel * 16));
                bfr[nb * 2][0]     = r0;  bfr[nb * 2][1]     = r2;
                bfr[nb * 2 + 1][0] = r1;  bfr[nb * 2 + 1][1] = r3;
            }

            #pragma unroll
            for (int mi = 0; mi < 4; ++mi)
                #pragma unroll
                for (int nj = 0; nj < 8; ++nj)
                    MMA_BF16(acc[mi][nj], af[mi], bfr[nj]);
        }
    }

    const size_t crow = ((size_t)b * N_ + m0 + wm0) * N_ + n0 + wn0;
    const int r     = lane >> 2;
    const int cpair = (lane & 3) * 2;
    #pragma unroll
    for (int mi = 0; mi < 4; ++mi) {
        #pragma unroll
        for (int nj = 0; nj < 8; ++nj) {
            const size_t off0 = crow + (size_t)(mi * 16 + r) * N_ + nj * 8 + cpair;
            *(float2*)(C + off0) = make_float2(acc[mi][nj][0], acc[mi][nj][1]);
            *(float2*)(C + off0 + (size_t)8 * N_) =
                make_float2(acc[mi][nj][2], acc[mi][nj][3]);
        }
    }
}

// ===========================================================================
// Pass 5: tf32 mma (R8)
// ===========================================================================
#define P5T_STRIDE 68
#define P5T_TILE  (128 * P5T_STRIDE * 4)
#define P5T_BUF   (2 * P5T_TILE)
#define SMEM_P5T  (2 * P5T_BUF + 1024)

__global__ void __launch_bounds__(256)
tmma_out(const float* __restrict__ A,
         const float* __restrict__ Bt,
         float* __restrict__ C)
{
    extern __shared__ char dsm[];
    const uint32_t base = (smem_u32(dsm) + 1023) & ~1023u;
    char* dbase = dsm + (base - smem_u32(dsm));

    const int tid  = threadIdx.x;
    const int lane = tid & 31;
    const int wid  = tid >> 5;
    const int wm0  = (wid & 1) * 64;
    const int wn0  = (wid >> 1) * 32;
    const int lg   = lane >> 2;
    const int lt   = lane & 3;

    const int b  = blockIdx.z;
    const int m0 = blockIdx.y * 128;
    const int n0 = blockIdx.x * 128;
    const char* Ab  = (const char*)(A  + ((size_t)b * N_ + m0) * N_);
    const char* Bb  = (const char*)(Bt + ((size_t)b * D_ + n0) * N_);
    const int ldAB = N_ * 4;

    float4 ar[8];

    auto ldg_A = [&](int kt) {
        #pragma unroll
        for (int i = 0; i < 8; ++i) {
            const int id  = tid + 256 * i;
            const int row = id >> 4;
            const int c16 = id & 15;
            ar[i] = *(const float4*)(Ab + (size_t)row * ldAB
                                        + (size_t)kt * 256 + c16 * 16);
        }
    };
    auto sts_A = [&](int buf) {
        uint32_t* sA = (uint32_t*)(dbase + buf * P5T_BUF);
        #pragma unroll
        for (int i = 0; i < 8; ++i) {
            const int id  = tid + 256 * i;
            const int row = id >> 4;
            const int c16 = id & 15;
            uint4 t;
            t.x = f2tf32(ar[i].x);
            t.y = f2tf32(ar[i].y);
            t.z = f2tf32(ar[i].z);
            t.w = f2tf32(ar[i].w);
            *(uint4*)(sA + row * P5T_STRIDE + c16 * 4) = t;
        }
    };
    auto ldB = [&](int buf, int kt) {
        const uint32_t sB = base + buf * P5T_BUF + P5T_TILE;
        const char* g = Bb + (size_t)kt * 256;
        #pragma unroll
        for (int i = 0; i < 8; ++i) {
            const int id  = tid + 256 * i;
            const int row = id >> 4;
            const int c16 = id & 15;
            CP_ASYNC_16(sB + row * (P5T_STRIDE * 4) + c16 * 16,
                        g + (size_t)row * ldAB + c16 * 16);
        }
    };

    float acc[4][4][4];
    #pragma unroll
    for (int i = 0; i < 4; ++i)
        #pragma unroll
        for (int j = 0; j < 4; ++j)
            #pragma unroll
            for (int r = 0; r < 4; ++r) acc[i][j][r] = 0.0f;

    ldB(0, 0);
    CP_ASYNC_COMMIT();
    ldg_A(0);
    sts_A(0);
    CP_ASYNC_WAIT_ALL();
    __syncthreads();

    const int KITER = N_ / 64;
    for (int kt = 0; kt < KITER; ++kt) {
        const int buf = kt & 1;
        const uint32_t* sA = (const uint32_t*)(dbase + buf * P5T_BUF);
        const float*    sB = (const float*)(dbase + buf * P5T_BUF + P5T_TILE);

        if (kt + 1 < KITER) {
            ldB(buf ^ 1, kt + 1);
            CP_ASYNC_COMMIT();
            ldg_A(kt + 1);
        }

        #pragma unroll
        for (int s = 0; s < 8; ++s) {
            const int k0 = s * 8;
            uint32_t af[4][4];
            uint32_t bf[4][2];

            #pragma unroll
            for (int mi = 0; mi < 4; ++mi) {
                const int rb = (wm0 + mi * 16 + lg) * P5T_STRIDE + k0 + lt;
                af[mi][0] = sA[rb];
                af[mi][1] = sA[rb + 8 * P5T_STRIDE];
                af[mi][2] = sA[rb + 4];
                af[mi][3] = sA[rb + 8 * P5T_STRIDE + 4];
            }
            #pragma unroll
            for (int nj = 0; nj < 4; ++nj) {
                const int rb = (wn0 + nj * 8 + lg) * P5T_STRIDE + k0 + lt;
                bf[nj][0] = f2tf32(sB[rb]);
                bf[nj][1] = f2tf32(sB[rb + 4]);
            }

            #pragma unroll
            for (int mi = 0; mi < 4; ++mi)
                #pragma unroll
                for (int nj = 0; nj < 4; ++nj)
                    MMA_TF32(acc[mi][nj], af[mi], bf[nj]);
        }

        if (kt + 1 < KITER) {
            __syncthreads();
            sts_A(buf ^ 1);
            CP_ASYNC_WAIT_ALL();
            __syncthreads();
        }
    }

    float* Cb = C + ((size_t)b * N_ + m0 + wm0) * D_ + n0 + wn0;
    const int cpair = lt * 2;
    #pragma unroll
    for (int mi = 0; mi < 4; ++mi) {
        #pragma unroll
        for (int nj = 0; nj < 4; ++nj) {
            float* p = Cb + (size_t)(mi * 16 + lg) * D_ + nj * 8 + cpair;
            *(float2*)p            = make_float2(acc[mi][nj][0], acc[mi][nj][1]);
            *(float2*)(p + 8 * D_) = make_float2(acc[mi][nj][2], acc[mi][nj][3]);
        }
    }
}

// ===========================================================================
// small kernels
// ===========================================================================
__global__ __launch_bounds__(256)
void split_f32(const float* __restrict__ X, bf16* __restrict__ H,
               bf16* __restrict__ L, size_t n4)
{
    size_t i = (size_t)blockIdx.x * blockDim.x + threadIdx.x;
    if (i >= n4) return;
    float4 v = ((const float4*)X)[i];
    float f[4] = {v.x, v.y, v.z, v.w};
    __nv_bfloat162 hh[2], ll[2];
    #pragma unroll
    for (int j = 0; j < 2; ++j) {
        bf16 h0 = __float2bfloat16(f[2 * j]);
        bf16 h1 = __float2bfloat16(f[2 * j + 1]);
        hh[j].x = h0; hh[j].y = h1;
        ll[j].x = __float2bfloat16(f[2 * j]     - __bfloat162float(h0));
        ll[j].y = __float2bfloat16(f[2 * j + 1] - __bfloat162float(h1));
    }
    ((uint2*)H)[i] = *(uint2*)hh;
    ((uint2*)L)[i] = *(uint2*)ll;
}

__global__ __launch_bounds__(256)
void wtrans_split3(const float* __restrict__ W0, const float* __restrict__ W1,
                   const float* __restrict__ W2,
                   const float* __restrict__ b0, const float* __restrict__ b1,
                   const float* __restrict__ b2,
                   bf16* __restrict__ Th, bf16* __restrict__ Tl,
                   float* __restrict__ gbias)
{
    __shared__ float t[32][33];
    const int z = blockIdx.z;
    const float* W = (z == 0) ? W0 : (z == 1) ? W1 : W2;
    const float* bz = (z == 0) ? b0 : (z == 1) ? b1 : b2;
    bf16* Thz = Th + z * D_ * D_;
    bf16* Tlz = Tl + z * D_ * D_;
    if (blockIdx.x == 0 && blockIdx.y == 0)
        gbias[z * D_ + threadIdx.x] = bz[threadIdx.x];
    const int x0 = blockIdx.x * 32;
    const int y0 = blockIdx.y * 32;
    const int tx = threadIdx.x & 31;
    const int ty = threadIdx.x >> 5;
    #pragma unroll
    for (int j = 0; j < 4; ++j)
        t[ty + 8 * j][tx] = W[(y0 + ty + 8 * j) * D_ + x0 + tx];
    __syncthreads();
    #pragma unroll
    for (int j = 0; j < 4; ++j) {
        float val = t[tx][ty + 8 * j];
        bf16 hi = __float2bfloat16(val);
        const int off = (x0 + ty + 8 * j) * D_ + y0 + tx;
        Thz[off] = hi;
        Tlz[off] = __float2bfloat16(val - __bfloat162float(hi));
    }
}

__global__ __launch_bounds__(256)
void softmax_warp(const bf16* __restrict__ S, bf16* __restrict__ O, float scale)
{
    const int lane = threadIdx.x & 31;
    const int w    = threadIdx.x >> 5;
    const size_t row = (size_t)blockIdx.x * 8 + w;
    const uint4* p = (const uint4*)(S + row * N_);
    uint4* o       = (uint4*)(O + row * N_);

    float vals[64];
    float m = -1e30f;
    #pragma unroll
    for (int c = 0; c < 8; ++c) {
        uint4 raw = p[c * 32 + lane];
        __nv_bfloat162* pr = (__nv_bfloat162*)&raw;
        #pragma unroll
        for (int i = 0; i < 4; ++i) {
            float2 f = __bfloat1622float2(pr[i]);
            vals[c * 8 + 2 * i]     = f.x * scale;
            vals[c * 8 + 2 * i + 1] = f.y * scale;
            m = fmaxf(m, fmaxf(f.x * scale, f.y * scale));
        }
    }
    #pragma unroll
    for (int s = 16; s > 0; s >>= 1)
        m = fmaxf(m, __shfl_xor_sync(0xFFFFFFFFu, m, s));

    float sum = 0.0f;
    #pragma unroll
    for (int i = 0; i < 64; ++i) {
        vals[i] = __expf(vals[i] - m);
        sum += vals[i];
    }
    #pragma unroll
    for (int s = 16; s > 0; s >>= 1)
        sum += __shfl_xor_sync(0xFFFFFFFFu, sum, s);
    const float inv = 1.0f / sum;

    #pragma unroll
    for (int c = 0; c < 8; ++c) {
        uint4 outv;
        __nv_bfloat162* po = (__nv_bfloat162*)&outv;
        #pragma unroll
        for (int i = 0; i < 4; ++i) {
            po[i].x = __float2bfloat16(vals[c * 8 + 2 * i] * inv);
            po[i].y = __float2bfloat16(vals[c * 8 + 2 * i + 1] * inv);
        }
        o[c * 32 + lane] = outv;
    }
}

__global__ __launch_bounds__(256)
void transpose_bf16(const float* __restrict__ A, bf16* __restrict__ T)
{
    __shared__ float t[32][33];
    const int b  = blockIdx.z;
    const int x0 = blockIdx.x * 32;
    const int y0 = blockIdx.y * 32;
    const float* Ab = A + (size_t)b * N_ * N_;
    bf16* Tb = T + (size_t)b * N_ * N_;
    const int tx = threadIdx.x & 31;
    const int ty = threadIdx.x >> 5;
    #pragma unroll
    for (int j = 0; j < 4; ++j)
        t[ty + 8 * j][tx] = Ab[(size_t)(y0 + ty + 8 * j) * N_ + x0 + tx];
    __syncthreads();
    #pragma unroll
    for (int j = 0; j < 4; ++j)
        Tb[(size_t)(x0 + ty + 8 * j) * N_ + y0 + tx] =
            __float2bfloat16(t[tx][ty + 8 * j]);
}

// ===========================================================================
extern "C" void kernel_launch(void* const* d_in, const int* in_sizes, int n_in,
                              void* d_out, int out_size)
{
    const float* text = (const float*)d_in[0];
    const float* adj  = (const float*)d_in[1];
    const float* Wq   = (const float*)d_in[2];
    const float* bq   = (const float*)d_in[3];
    const float* Wk   = (const float*)d_in[4];
    const float* bk   = (const float*)d_in[5];
    const float* Wv   = (const float*)d_in[6];
    const float* bv   = (const float*)d_in[7];

    float* out     = (float*)d_out;
    float* new_adj = out + (long long)B_ * N_ * D_;

    bf16 *pth, *ptl, *pwth, *pwtl, *pqk, *pattn, *padjT;
    float *pvt, *ps, *pbias;
    cudaGetSymbolAddress((void**)&pth,  g_texth);
    cudaGetSymbolAddress((void**)&ptl,  g_textl);
    cudaGetSymbolAddress((void**)&pwth, g_wth);
    cudaGetSymbolAddress((void**)&pwtl, g_wtl);
    cudaGetSymbolAddress((void**)&pbias, g_bias);
    cudaGetSymbolAddress((void**)&pqk,  g_qkb);
    cudaGetSymbolAddress((void**)&pvt,  g_vt);
    cudaGetSymbolAddress((void**)&ps,   g_s);
    cudaGetSymbolAddress((void**)&pattn, g_attn);
    cudaGetSymbolAddress((void**)&padjT, g_adjT);

    bf16* psb = (bf16*)ps;

    const int SMEM_G1 = 2 * 2 * HTILE + 1024;
    cudaFuncSetAttribute((const void*)hmma_g<1, bf16>,
                         cudaFuncAttributeMaxDynamicSharedMemorySize, SMEM_G1);
    cudaFuncSetAttribute((const void*)hmma_qkv,
                         cudaFuncAttributeMaxDynamicSharedMemorySize, SMEM_QKV);
    cudaFuncSetAttribute((const void*)hmma_p4,
                         cudaFuncAttributeMaxDynamicSharedMemorySize, SMEM_P4);
    cudaFuncSetAttribute((const void*)tmma_out,
                         cudaFuncAttributeMaxDynamicSharedMemorySize, SMEM_P5T);

    const dim3 t(256);
    const long long sQK = (long long)N_ * 512;
    const long long sS  = (long long)N_ * N_;

    // pre: split text; transpose+split weights + bias concat
    {
        const size_t n4 = (size_t)B_ * N_ * D_ / 4;
        split_f32<<<(unsigned)((n4 + 255) / 256), t>>>(text, pth, ptl, n4);
        dim3 g(D_ / 32, D_ / 32, 3);
        wtrans_split3<<<g, t>>>(Wq, Wk, Wv, bq, bk, bv, pwth, pwtl, pbias);
    }

    // adjT (independent)
    {
        dim3 g(N_ / 32, N_ / 32, B_);
        transpose_bf16<<<g, t>>>(adj, padjT);
    }

    // pass 1: fused q|k|v projection; v written directly transposed (vT)
    {
        dim3 g(768 / 128, (B_ * N_) / 128, 1);   // (6, 128, 1)
        hmma_qkv<<<g, t, SMEM_QKV>>>(pth, ptl, pwth, pwtl, pbias, pqk, pvt);
    }

    // pass 2: S = q @ k^T -> bf16
    {
        dim3 g(N_ / 128, N_ / 128, B_);
        hmma_g<1, bf16><<<g, t, SMEM_G1>>>(
            pqk, pqk + 256, psb, D_ / 64, 512, 512, N_, sQK, sQK, sS);
    }

    // pass 3: softmax (warp per row)
    softmax_warp<<<B_ * N_ / 8, t>>>(psb, pattn, 1.0f / 16.0f);

    // pass 4: new_adj = attn @ adjT^T
    {
        dim3 g(N_ / 256, N_ / 128, B_);
        hmma_p4<<<g, t, SMEM_P4>>>(pattn, padjT, new_adj);
    }

    // pass 5: out = new_adj @ vT^T  (tf32)
    {
        dim3 g(D_ / 128, N_ / 128, B_);
        tmma_out<<<g, t, SMEM_P5T>>>(new_adj, pvt, out);
    }
}

// round 14
// speedup vs baseline: 1.0313x; 1.0086x over previous
#include <cuda_runtime.h>
#include <cuda_bf16.h>
#include <cstdint>

// ---------------------------------------------------------------------------
// AttentionGNN Round 13 = R12 + prep fusion:
//   split_f32 + wtrans_split3 + transpose_bf16 merged into ONE flat-grid
//   kernel (all DRAM-bound, mutually independent -> overlap instead of
//   serialize). Per-element logic unchanged -> bit-identical results.
// ---------------------------------------------------------------------------

#define B_   8
#define N_   2048
#define D_   256

typedef __nv_bfloat16 bf16;

// Scratch (device globals)
__device__ bf16  g_texth[(size_t)B_ * N_ * D_];
__device__ bf16  g_textl[(size_t)B_ * N_ * D_];
__device__ bf16  g_wth[3 * D_ * D_];            // WqT|WkT|WvT hi (768x256)
__device__ bf16  g_wtl[3 * D_ * D_];
__device__ float g_bias[3 * D_];                // bq|bk|bv
__device__ bf16  g_qkb[(size_t)B_ * N_ * 512];  // q|k per row
__device__ float g_vt [(size_t)B_ * D_ * N_];   // v^T fp32
__device__ float g_s  [(size_t)B_ * N_ * N_];
__device__ bf16  g_attn[(size_t)B_ * N_ * N_];
__device__ bf16  g_adjT[(size_t)B_ * N_ * N_];

// ===========================================================================
// helpers
// ===========================================================================
__device__ __forceinline__ uint32_t smem_u32(const void* p) {
    uint32_t a;
    asm("{ .reg .u64 t; cvta.to.shared.u64 t, %1; cvt.u32.u64 %0, t; }"
        : "=r"(a) : "l"(p));
    return a;
}

#define SMEM_SWIZZLE_128B(off) ((off) ^ (((off) >> 3) & 0x70))

#define CP_ASYNC_16(dst, src) \
    asm volatile("cp.async.cg.shared.global [%0], [%1], 16;" \
                 :: "r"(dst), "l"(src) : "memory")
#define CP_ASYNC_COMMIT() asm volatile("cp.async.commit_group;" ::: "memory")
#define CP_ASYNC_WAIT_ALL() asm volatile("cp.async.wait_group 0;" ::: "memory")
#define CP_ASYNC_WAIT_1()  asm volatile("cp.async.wait_group 1;" ::: "memory")

#define LDMATRIX_X4(r0, r1, r2, r3, addr) \
    asm volatile("ldmatrix.sync.aligned.m8n8.x4.shared.b16 {%0,%1,%2,%3}, [%4];" \
                 : "=r"(r0), "=r"(r1), "=r"(r2), "=r"(r3) : "r"(addr))

#define MMA_BF16(d, a, b) \
    asm volatile("mma.sync.aligned.m16n8k16.row.col.f32.bf16.bf16.f32 " \
                 "{%0,%1,%2,%3}, {%4,%5,%6,%7}, {%8,%9}, {%0,%1,%2,%3};" \
                 : "+f"((d)[0]), "+f"((d)[1]), "+f"((d)[2]), "+f"((d)[3]) \
                 : "r"((a)[0]), "r"((a)[1]), "r"((a)[2]), "r"((a)[3]), \
                   "r"((b)[0]), "r"((b)[1]))

#define MMA_TF32(d, a, b) \
    asm volatile("mma.sync.aligned.m16n8k8.row.col.f32.tf32.tf32.f32 " \
                 "{%0,%1,%2,%3}, {%4,%5,%6,%7}, {%8,%9}, {%0,%1,%2,%3};" \
                 : "+f"((d)[0]), "+f"((d)[1]), "+f"((d)[2]), "+f"((d)[3]) \
                 : "r"((a)[0]), "r"((a)[1]), "r"((a)[2]), "r"((a)[3]), \
                   "r"((b)[0]), "r"((b)[1]))

__device__ __forceinline__ uint32_t f2tf32(float f) {
    uint32_t r;
    asm("cvt.rna.tf32.f32 %0, %1;" : "=r"(r) : "f"(f));
    return r;
}

#define HTILE 16384

template <int ROWS>
__device__ __forceinline__ void load_tileR(
    uint32_t s, const char* gbase, int ldBytes, int tid)
{
    #pragma unroll
    for (int i = 0; i < ROWS / 32; ++i) {
        int id  = tid + 256 * i;
        int row = id >> 3;
        int c   = (id & 7) * 16;
        CP_ASYNC_16(s + SMEM_SWIZZLE_128B(row * 128 + c),
                    gbase + (size_t)row * ldBytes + c);
    }
}

__device__ __forceinline__ void store2(float* p, float a, float b) {
    *(float2*)p = make_float2(a, b);
}
__device__ __forceinline__ void store2(bf16* p, float a, float b) {
    __nv_bfloat162 h;
    h.x = __float2bfloat16(a);
    h.y = __float2bfloat16(b);
    *(__nv_bfloat162*)p = h;
}

// ===========================================================================
// PREP (fused): flat grid dispatches three independent DRAM-bound jobs.
//   [0, 32768)          : adj fp32 -> adjT bf16 (32x32 tiles)
//   [32768, 36864)      : text -> texth/textl split (float4 chunks)
//   [36864, 37056)      : W -> W^T hi/lo + bias concat
// ===========================================================================
#define PREP_ADJT  32768
#define PREP_SPLIT 4096
#define PREP_W     192
#define PREP_BLOCKS (PREP_ADJT + PREP_SPLIT + PREP_W)

__global__ __launch_bounds__(256)
void prep_all(const float* __restrict__ adj,  bf16* __restrict__ adjT,
              const float* __restrict__ text, bf16* __restrict__ th,
              bf16* __restrict__ tl,
              const float* __restrict__ W0, const float* __restrict__ W1,
              const float* __restrict__ W2,
              const float* __restrict__ b0, const float* __restrict__ b1,
              const float* __restrict__ b2,
              bf16* __restrict__ Wh, bf16* __restrict__ Wl,
              float* __restrict__ gbias)
{
    __shared__ float t[32][33];
    const int bid = blockIdx.x;
    const int tx  = threadIdx.x & 31;
    const int ty  = threadIdx.x >> 5;

    if (bid < PREP_ADJT) {
        // adjT tile: z = bid/4096, y = (bid%4096)/64, x = bid%64
        const int z  = bid >> 12;
        const int rem = bid & 4095;
        const int y0 = (rem >> 6) * 32;
        const int x0 = (rem & 63) * 32;
        const float* Ab = adj + (size_t)z * N_ * N_;
        bf16* Tb = adjT + (size_t)z * N_ * N_;
        #pragma unroll
        for (int j = 0; j < 4; ++j)
            t[ty + 8 * j][tx] = Ab[(size_t)(y0 + ty + 8 * j) * N_ + x0 + tx];
        __syncthreads();
        #pragma unroll
        for (int j = 0; j < 4; ++j)
            Tb[(size_t)(x0 + ty + 8 * j) * N_ + y0 + tx] =
                __float2bfloat16(t[tx][ty + 8 * j]);
    } else if (bid < PREP_ADJT + PREP_SPLIT) {
        // text split: same math as split_f32
        const size_t i = (size_t)(bid - PREP_ADJT) * 256 + threadIdx.x;
        float4 v = ((const float4*)text)[i];
        float f[4] = {v.x, v.y, v.z, v.w};
        __nv_bfloat162 hh[2], ll[2];
        #pragma unroll
        for (int j = 0; j < 2; ++j) {
            bf16 h0 = __float2bfloat16(f[2 * j]);
            bf16 h1 = __float2bfloat16(f[2 * j + 1]);
            hh[j].x = h0; hh[j].y = h1;
            ll[j].x = __float2bfloat16(f[2 * j]     - __bfloat162float(h0));
            ll[j].y = __float2bfloat16(f[2 * j + 1] - __bfloat162float(h1));
        }
        ((uint2*)th)[i] = *(uint2*)hh;
        ((uint2*)tl)[i] = *(uint2*)ll;
    } else {
        // W transpose+split: w = 0..191; z = w/64; rem: y = rem>>3, x = rem&7
        const int w  = bid - (PREP_ADJT + PREP_SPLIT);
        const int z  = w >> 6;
        const int rem = w & 63;
        const int y0 = (rem >> 3) * 32;
        const int x0 = (rem & 7) * 32;
        const float* W = (z == 0) ? W0 : (z == 1) ? W1 : W2;
        const float* bz = (z == 0) ? b0 : (z == 1) ? b1 : b2;
        bf16* Thz = Wh + z * D_ * D_;
        bf16* Tlz = Wl + z * D_ * D_;
        if (x0 == 0 && y0 == 0)
            gbias[z * D_ + threadIdx.x] = bz[threadIdx.x];
        #pragma unroll
        for (int j = 0; j < 4; ++j)
            t[ty + 8 * j][tx] = W[(y0 + ty + 8 * j) * D_ + x0 + tx];
        __syncthreads();
        #pragma unroll
        for (int j = 0; j < 4; ++j) {
            float val = t[tx][ty + 8 * j];
            bf16 hi = __float2bfloat16(val);
            const int off = (x0 + ty + 8 * j) * D_ + y0 + tx;
            Thz[off] = hi;
            Tlz[off] = __float2bfloat16(val - __bfloat162float(hi));
        }
    }
}

// ===========================================================================
// Fused QKV projection (R12): q,k 2-term bf16; v 3-term, written transposed.
// ===========================================================================
#define SMEM_QKV (2 * 4 * HTILE + 1024)
#define VT_S 132

__global__ void __launch_bounds__(256)
hmma_qkv(const bf16* __restrict__ Ah, const bf16* __restrict__ Al,
         const bf16* __restrict__ Bh, const bf16* __restrict__ Bl,
         const float* __restrict__ gbias,
         bf16* __restrict__ Cqk, float* __restrict__ Cvt)
{
    extern __shared__ char dsm[];
    const uint32_t base = (smem_u32(dsm) + 1023) & ~1023u;
    float* stage = (float*)(dsm + (base - smem_u32(dsm)));
    constexpr uint32_t OAL = HTILE;
    constexpr uint32_t OBH = 2u * HTILE;
    constexpr uint32_t OBL = 3u * HTILE;
    constexpr int TPB = 4;

    const int tid  = threadIdx.x;
    const int lane = tid & 31;
    const int wid  = tid >> 5;
    const int wm0  = (wid & 1) * 64;
    const int wn0  = (wid >> 1) * 32;
    const int lr   = lane & 15;
    const int lc   = lane >> 4;

    const int m0 = blockIdx.y * 128;
    const int n0 = blockIdx.x * 128;
    const bool isV = (n0 >= 512);
    const char* Ahb = (const char*)(Ah + (size_t)m0 * D_);
    const char* Alb = (const char*)(Al + (size_t)m0 * D_);
    const char* Bhb = (const char*)(Bh + (size_t)n0 * D_);
    const char* Blb = (const char*)(Bl + (size_t)n0 * D_);
    const int ldAB = D_ * 2;

    float acc[4][4][4];
    #pragma unroll
    for (int i = 0; i < 4; ++i)
        #pragma unroll
        for (int j = 0; j < 4; ++j)
            #pragma unroll
            for (int r = 0; r < 4; ++r) acc[i][j][r] = 0.0f;

    load_tileR<128>(base,       Ahb, ldAB, tid);
    load_tileR<128>(base + OAL, Alb, ldAB, tid);
    load_tileR<128>(base + OBH, Bhb, ldAB, tid);
    if (isV) load_tileR<128>(base + OBL, Blb, ldAB, tid);
    CP_ASYNC_COMMIT();
    CP_ASYNC_WAIT_ALL();
    __syncthreads();

    const int kIters = D_ / 64;
    for (int kt = 0; kt < kIters; ++kt) {
        const int buf = kt & 1;
        const uint32_t cAh = base + buf * (TPB * HTILE);
        const uint32_t cAl = cAh + OAL;
        const uint32_t cBh = cAh + OBH;
        const uint32_t cBl = cAh + OBL;

        if (kt + 1 < kIters) {
            const uint32_t nx = base + (buf ^ 1) * (TPB * HTILE);
            const size_t ko = (size_t)(kt + 1) * 128;
            load_tileR<128>(nx,       Ahb + ko, ldAB, tid);
            load_tileR<128>(nx + OAL, Alb + ko, ldAB, tid);
            load_tileR<128>(nx + OBH, Bhb + ko, ldAB, tid);
            if (isV) load_tileR<128>(nx + OBL, Blb + ko, ldAB, tid);
            CP_ASYNC_COMMIT();
        }

        #pragma unroll
        for (int ks = 0; ks < 4; ++ks) {
            uint32_t afh[4][4], afl[4][4];
            uint32_t bfh[4][2], bfl[4][2];
            const int csel = ks * 2 + lc;

            #pragma unroll
            for (int mi = 0; mi < 4; ++mi) {
                const int row = wm0 + mi * 16 + lr;
                const uint32_t so = SMEM_SWIZZLE_128B(row * 128 + csel * 16);
                LDMATRIX_X4(afh[mi][0], afh[mi][1], afh[mi][2], afh[mi][3], cAh + so);
                LDMATRIX_X4(afl[mi][0], afl[mi][1], afl[mi][2], afl[mi][3], cAl + so);
            }
            #pragma unroll
            for (int nb = 0; nb < 2; ++nb) {
                const int row = wn0 + nb * 16 + lr;
                const uint32_t so = SMEM_SWIZZLE_128B(row * 128 + csel * 16);
                uint32_t r0, r1, r2, r3;
                LDMATRIX_X4(r0, r1, r2, r3, cBh + so);
                bfh[nb * 2][0]     = r0;  bfh[nb * 2][1]     = r2;
                bfh[nb * 2 + 1][0] = r1;  bfh[nb * 2 + 1][1] = r3;
                if (isV) {
                    LDMATRIX_X4(r0, r1, r2, r3, cBl + so);
                    bfl[nb * 2][0]     = r0;  bfl[nb * 2][1]     = r2;
                    bfl[nb * 2 + 1][0] = r1;  bfl[nb * 2 + 1][1] = r3;
                }
            }

            #pragma unroll
            for (int mi = 0; mi < 4; ++mi)
                #pragma unroll
                for (int nj = 0; nj < 4; ++nj) {
                    MMA_BF16(acc[mi][nj], afh[mi], bfh[nj]);
                    MMA_BF16(acc[mi][nj], afl[mi], bfh[nj]);
                }
            if (isV) {
                #pragma unroll
                for (int mi = 0; mi < 4; ++mi)
                    #pragma unroll
                    for (int nj = 0; nj < 4; ++nj)
                        MMA_BF16(acc[mi][nj], afh[mi], bfl[nj]);
            }
        }

        CP_ASYNC_WAIT_ALL();
        __syncthreads();
    }

    const int r     = lane >> 2;
    const int cpair = (lane & 3) * 2;

    if (!isV) {
        #pragma unroll
        for (int mi = 0; mi < 4; ++mi) {
            #pragma unroll
            for (int nj = 0; nj < 4; ++nj) {
                const int col = n0 + wn0 + nj * 8 + cpair;
                const float b0 = gbias[col], b1 = gbias[col + 1];
                const int row0 = m0 + wm0 + mi * 16 + r;
                bf16* p = Cqk + (size_t)row0 * 512 + col;
                store2(p, acc[mi][nj][0] + b0, acc[mi][nj][1] + b1);
                store2(p + (size_t)8 * 512, acc[mi][nj][2] + b0, acc[mi][nj][3] + b1);
            }
        }
    } else {
        #pragma unroll
        for (int mi = 0; mi < 4; ++mi) {
            #pragma unroll
            for (int nj = 0; nj < 4; ++nj) {
                const int col = n0 + wn0 + nj * 8 + cpair;
                const float b0 = gbias[col], b1 = gbias[col + 1];
                const int dl  = (col - n0);
                const int rl0 = wm0 + mi * 16 + r;
                stage[(size_t)dl * VT_S + rl0]           = acc[mi][nj][0] + b0;
                stage[(size_t)(dl + 1) * VT_S + rl0]     = acc[mi][nj][1] + b1;
                stage[(size_t)dl * VT_S + rl0 + 8]       = acc[mi][nj][2] + b0;
                stage[(size_t)(dl + 1) * VT_S + rl0 + 8] = acc[mi][nj][3] + b1;
            }
        }
        __syncthreads();

        const int bz    = m0 >> 11;
        const int nrow0 = m0 & 2047;
        const int d0    = n0 - 512;
        const int nn  = (tid & 31) * 4;
        const int dw  = tid >> 5;
        #pragma unroll
        for (int dd = 0; dd < 16; ++dd) {
            const int d = dw + dd * 8;
            const float* s = stage + (size_t)d * VT_S + nn;
            float4 v4 = make_float4(s[0], s[1], s[2], s[3]);
            *(float4*)(Cvt + ((size_t)bz * D_ + d0 + d) * N_ + nrow0 + nn) = v4;
        }
    }
}

// ===========================================================================
// Generic NT bf16 HMMA GEMM, CTA 128x128 — pass 2.
// ===========================================================================
template <int TERMS, typename OutT>
__global__ void __launch_bounds__(256, TERMS == 1 ? 2 : 1)
hmma_g(const bf16* __restrict__ Ah, const bf16* __restrict__ Bh,
       OutT* __restrict__ C,
       int kIters, int ldA, int ldB, int ldC,
       long long sA, long long sB, long long sC)
{
    extern __shared__ char dsm[];
    const uint32_t base = (smem_u32(dsm) + 1023) & ~1023u;
    constexpr int TPB = 2;
    constexpr uint32_t OBH = HTILE;

    const int tid  = threadIdx.x;
    const int lane = tid & 31;
    const int wid  = tid >> 5;
    const int wm0  = (wid & 1) * 64;
    const int wn0  = (wid >> 1) * 32;
    const int lr   = lane & 15;
    const int lc   = lane >> 4;

    const int b  = blockIdx.z;
    const int m0 = blockIdx.y * 128;
    const int n0 = blockIdx.x * 128;
    const char* Ahb = (const char*)(Ah + (size_t)b * sA + (size_t)m0 * ldA);
    const char* Bhb = (const char*)(Bh + (size_t)b * sB + (size_t)n0 * ldB);
    const int ldAB = ldA * 2;
    const int ldBB = ldB * 2;

    float acc[4][4][4];
    #pragma unroll
    for (int i = 0; i < 4; ++i)
        #pragma unroll
        for (int j = 0; j < 4; ++j)
            #pragma unroll
            for (int r = 0; r < 4; ++r) acc[i][j][r] = 0.0f;

    load_tileR<128>(base,       Ahb, ldAB, tid);
    load_tileR<128>(base + OBH, Bhb, ldBB, tid);
    CP_ASYNC_COMMIT();
    CP_ASYNC_WAIT_ALL();
    __syncthreads();

    for (int kt = 0; kt < kIters; ++kt) {
        const int buf = kt & 1;
        const uint32_t cAh = base + buf * (TPB * HTILE);
        const uint32_t cBh = cAh + OBH;

        if (kt + 1 < kIters) {
            const uint32_t nx = base + (buf ^ 1) * (TPB * HTILE);
            const size_t ko = (size_t)(kt + 1) * 128;
            load_tileR<128>(nx,       Ahb + ko, ldAB, tid);
            load_tileR<128>(nx + OBH, Bhb + ko, ldBB, tid);
            CP_ASYNC_COMMIT();
        }

        #pragma unroll
        for (int ks = 0; ks < 4; ++ks) {
            uint32_t af[4][4];
            uint32_t bfr[4][2];
            const int csel = ks * 2 + lc;

            #pragma unroll
            for (int mi = 0; mi < 4; ++mi) {
                const int row = wm0 + mi * 16 + lr;
                LDMATRIX_X4(af[mi][0], af[mi][1], af[mi][2], af[mi][3],
                            cAh + SMEM_SWIZZLE_128B(row * 128 + csel * 16));
            }
            #pragma unroll
            for (int nb = 0; nb < 2; ++nb) {
                const int row = wn0 + nb * 16 + lr;
                uint32_t r0, r1, r2, r3;
                LDMATRIX_X4(r0, r1, r2, r3,
                            cBh + SMEM_SWIZZLE_128B(row * 128 + csel * 16));
                bfr[nb * 2][0]     = r0;  bfr[nb * 2][1]     = r2;
                bfr[nb * 2 + 1][0] = r1;  bfr[nb * 2 + 1][1] = r3;
            }

            #pragma unroll
            for (int mi = 0; mi < 4; ++mi)
                #pragma unroll
                for (int nj = 0; nj < 4; ++nj)
                    MMA_BF16(acc[mi][nj], af[mi], bfr[nj]);
        }

        CP_ASYNC_WAIT_ALL();
        __syncthreads();
    }

    const size_t crow = (size_t)b * sC + (size_t)(m0 + wm0) * ldC + n0 + wn0;
    const int r     = lane >> 2;
    const int cpair = (lane & 3) * 2;
    #pragma unroll
    for (int mi = 0; mi < 4; ++mi) {
        #pragma unroll
        for (int nj = 0; nj < 4; ++nj) {
            const size_t off0 = crow + (size_t)(mi * 16 + r) * ldC + nj * 8 + cpair;
            store2(C + off0, acc[mi][nj][0], acc[mi][nj][1]);
            store2(C + off0 + (size_t)8 * ldC, acc[mi][nj][2], acc[mi][nj][3]);
        }
    }
}

// ===========================================================================
// Pass 4: bf16 HMMA, CTA 128x256, 3-stage pipeline (R8)
// ===========================================================================
#define P4_AT 16384
#define P4_BT 32768
#define P4_BUF (P4_AT + P4_BT)
#define SMEM_P4 (3 * P4_BUF + 1024)

__global__ void __launch_bounds__(256)
hmma_p4(const bf16* __restrict__ A, const bf16* __restrict__ Bt,
        float* __restrict__ C)
{
    extern __shared__ char dsm[];
    const uint32_t base = (smem_u32(dsm) + 1023) & ~1023u;

    const int tid  = threadIdx.x;
    const int lane = tid & 31;
    const int wid  = tid >> 5;
    const int wm0  = (wid & 1) * 64;
    const int wn0  = (wid >> 1) * 64;
    const int lr   = lane & 15;
    const int lc   = lane >> 4;

    const int b  = blockIdx.z;
    const int m0 = blockIdx.y * 128;
    const int n0 = blockIdx.x * 256;
    const char* Ab = (const char*)(A  + ((size_t)b * N_ + m0) * N_);
    const char* Bb = (const char*)(Bt + ((size_t)b * N_ + n0) * N_);
    const int ld = N_ * 2;

    float acc[4][8][4];
    #pragma unroll
    for (int i = 0; i < 4; ++i)
        #pragma unroll
        for (int j = 0; j < 8; ++j)
            #pragma unroll
            for (int r = 0; r < 4; ++r) acc[i][j][r] = 0.0f;

    const int KITER = N_ / 64;

    load_tileR<128>(base,         Ab, ld, tid);
    load_tileR<256>(base + P4_AT, Bb, ld, tid);
    CP_ASYNC_COMMIT();
    load_tileR<128>(base + P4_BUF,         Ab + 128, ld, tid);
    load_tileR<256>(base + P4_BUF + P4_AT, Bb + 128, ld, tid);
    CP_ASYNC_COMMIT();

    for (int kt = 0; kt < KITER; ++kt) {
        if (kt + 1 < KITER) { CP_ASYNC_WAIT_1(); } else { CP_ASYNC_WAIT_ALL(); }
        __syncthreads();

        if (kt + 2 < KITER) {
            const uint32_t nx = base + ((kt + 2) % 3) * P4_BUF;
            const size_t ko = (size_t)(kt + 2) * 128;
            load_tileR<128>(nx,         Ab + ko, ld, tid);
            load_tileR<256>(nx + P4_AT, Bb + ko, ld, tid);
            CP_ASYNC_COMMIT();
        }

        const uint32_t cA = base + (kt % 3) * P4_BUF;
        const uint32_t cB = cA + P4_AT;

        #pragma unroll
        for (int ks = 0; ks < 4; ++ks) {
            uint32_t af[4][4];
            uint32_t bfr[8][2];
            const int csel = ks * 2 + lc;

            #pragma unroll
            for (int mi = 0; mi < 4; ++mi) {
                const int row = wm0 + mi * 16 + lr;
                LDMATRIX_X4(af[mi][0], af[mi][1], af[mi][2], af[mi][3],
                            cA + SMEM_SWIZZLE_128B(row * 128 + csel * 16));
            }
            #pragma unroll
            for (int nb = 0; nb < 4; ++nb) {
                const int row = wn0 + nb * 16 + lr;
                uint32_t r0, r1, r2, r3;
                LDMATRIX_X4(r0, r1, r2, r3,
                            cB + SMEM_SWIZZLE_128B(row * 128 + csel * 16));
                bfr[nb * 2][0]     = r0;  bfr[nb * 2][1]     = r2;
                bfr[nb * 2 + 1][0] = r1;  bfr[nb * 2 + 1][1] = r3;
            }

            #pragma unroll
            for (int mi = 0; mi < 4; ++mi)
                #pragma unroll
                for (int nj = 0; nj < 8; ++nj)
                    MMA_BF16(acc[mi][nj], af[mi], bfr[nj]);
        }
    }

    const size_t crow = ((size_t)b * N_ + m0 + wm0) * N_ + n0 + wn0;
    const int r     = lane >> 2;
    const int cpair = (lane & 3) * 2;
    #pragma unroll
    for (int mi = 0; mi < 4; ++mi) {
        #pragma unroll
        for (int nj = 0; nj < 8; ++nj) {
            const size_t off0 = crow + (size_t)(mi * 16 + r) * N_ + nj * 8 + cpair;
            *(float2*)(C + off0) = make_float2(acc[mi][nj][0], acc[mi][nj][1]);
            *(float2*)(C + off0 + (size_t)8 * N_) =
                make_float2(acc[mi][nj][2], acc[mi][nj][3]);
        }
    }
}

// ===========================================================================
// Pass 5: tf32 mma (R8)
// ===========================================================================
#define P5T_STRIDE 68
#define P5T_TILE  (128 * P5T_STRIDE * 4)
#define P5T_BUF   (2 * P5T_TILE)
#define SMEM_P5T  (2 * P5T_BUF + 1024)

__global__ void __launch_bounds__(256)
tmma_out(const float* __restrict__ A,
         const float* __restrict__ Bt,
         float* __restrict__ C)
{
    extern __shared__ char dsm[];
    const uint32_t base = (smem_u32(dsm) + 1023) & ~1023u;
    char* dbase = dsm + (base - smem_u32(dsm));

    const int tid  = threadIdx.x;
    const int lane = tid & 31;
    const int wid  = tid >> 5;
    const int wm0  = (wid & 1) * 64;
    const int wn0  = (wid >> 1) * 32;
    const int lg   = lane >> 2;
    const int lt   = lane & 3;

    const int b  = blockIdx.z;
    const int m0 = blockIdx.y * 128;
    const int n0 = blockIdx.x * 128;
    const char* Ab  = (const char*)(A  + ((size_t)b * N_ + m0) * N_);
    const char* Bb  = (const char*)(Bt + ((size_t)b * D_ + n0) * N_);
    const int ldAB = N_ * 4;

    float4 ar[8];

    auto ldg_A = [&](int kt) {
        #pragma unroll
        for (int i = 0; i < 8; ++i) {
            const int id  = tid + 256 * i;
            const int row = id >> 4;
            const int c16 = id & 15;
            ar[i] = *(const float4*)(Ab + (size_t)row * ldAB
                                        + (size_t)kt * 256 + c16 * 16);
        }
    };
    auto sts_A = [&](int buf) {
        uint32_t* sA = (uint32_t*)(dbase + buf * P5T_BUF);
        #pragma unroll
        for (int i = 0; i < 8; ++i) {
            const int id  = tid + 256 * i;
            const int row = id >> 4;
            const int c16 = id & 15;
            uint4 t;
            t.x = f2tf32(ar[i].x);
            t.y = f2tf32(ar[i].y);
            t.z = f2tf32(ar[i].z);
            t.w = f2tf32(ar[i].w);
            *(uint4*)(sA + row * P5T_STRIDE + c16 * 4) = t;
        }
    };
    auto ldB = [&](int buf, int kt) {
        const uint32_t sB = base + buf * P5T_BUF + P5T_TILE;
        const char* g = Bb + (size_t)kt * 256;
        #pragma unroll
        for (int i = 0; i < 8; ++i) {
            const int id  = tid + 256 * i;
            const int row = id >> 4;
            const int c16 = id & 15;
            CP_ASYNC_16(sB + row * (P5T_STRIDE * 4) + c16 * 16,
                        g + (size_t)row * ldAB + c16 * 16);
        }
    };

    float acc[4][4][4];
    #pragma unroll
    for (int i = 0; i < 4; ++i)
        #pragma unroll
        for (int j = 0; j < 4; ++j)
            #pragma unroll
            for (int r = 0; r < 4; ++r) acc[i][j][r] = 0.0f;

    ldB(0, 0);
    CP_ASYNC_COMMIT();
    ldg_A(0);
    sts_A(0);
    CP_ASYNC_WAIT_ALL();
    __syncthreads();

    const int KITER = N_ / 64;
    for (int kt = 0; kt < KITER; ++kt) {
        const int buf = kt & 1;
        const uint32_t* sA = (const uint32_t*)(dbase + buf * P5T_BUF);
        const float*    sB = (const float*)(dbase + buf * P5T_BUF + P5T_TILE);

        if (kt + 1 < KITER) {
            ldB(buf ^ 1, kt + 1);
            CP_ASYNC_COMMIT();
            ldg_A(kt + 1);
        }

        #pragma unroll
        for (int s = 0; s < 8; ++s) {
            const int k0 = s * 8;
            uint32_t af[4][4];
            uint32_t bf[4][2];

            #pragma unroll
            for (int mi = 0; mi < 4; ++mi) {
                const int rb = (wm0 + mi * 16 + lg) * P5T_STRIDE + k0 + lt;
                af[mi][0] = sA[rb];
                af[mi][1] = sA[rb + 8 * P5T_STRIDE];
                af[mi][2] = sA[rb + 4];
                af[mi][3] = sA[rb + 8 * P5T_STRIDE + 4];
            }
            #pragma unroll
            for (int nj = 0; nj < 4; ++nj) {
                const int rb = (wn0 + nj * 8 + lg) * P5T_STRIDE + k0 + lt;
                bf[nj][0] = f2tf32(sB[rb]);
                bf[nj][1] = f2tf32(sB[rb + 4]);
            }

            #pragma unroll
            for (int mi = 0; mi < 4; ++mi)
                #pragma unroll
                for (int nj = 0; nj < 4; ++nj)
                    MMA_TF32(acc[mi][nj], af[mi], bf[nj]);
        }

        if (kt + 1 < KITER) {
            __syncthreads();
            sts_A(buf ^ 1);
            CP_ASYNC_WAIT_ALL();
            __syncthreads();
        }
    }

    float* Cb = C + ((size_t)b * N_ + m0 + wm0) * D_ + n0 + wn0;
    const int cpair = lt * 2;
    #pragma unroll
    for (int mi = 0; mi < 4; ++mi) {
        #pragma unroll
        for (int nj = 0; nj < 4; ++nj) {
            float* p = Cb + (size_t)(mi * 16 + lg) * D_ + nj * 8 + cpair;
            *(float2*)p            = make_float2(acc[mi][nj][0], acc[mi][nj][1]);
            *(float2*)(p + 8 * D_) = make_float2(acc[mi][nj][2], acc[mi][nj][3]);
        }
    }
}

// ===========================================================================
// softmax (warp per row)
// ===========================================================================
__global__ __launch_bounds__(256)
void softmax_warp(const bf16* __restrict__ S, bf16* __restrict__ O, float scale)
{
    const int lane = threadIdx.x & 31;
    const int w    = threadIdx.x >> 5;
    const size_t row = (size_t)blockIdx.x * 8 + w;
    const uint4* p = (const uint4*)(S + row * N_);
    uint4* o       = (uint4*)(O + row * N_);

    float vals[64];
    float m = -1e30f;
    #pragma unroll
    for (int c = 0; c < 8; ++c) {
        uint4 raw = p[c * 32 + lane];
        __nv_bfloat162* pr = (__nv_bfloat162*)&raw;
        #pragma unroll
        for (int i = 0; i < 4; ++i) {
            float2 f = __bfloat1622float2(pr[i]);
            vals[c * 8 + 2 * i]     = f.x * scale;
            vals[c * 8 + 2 * i + 1] = f.y * scale;
            m = fmaxf(m, fmaxf(f.x * scale, f.y * scale));
        }
    }
    #pragma unroll
    for (int s = 16; s > 0; s >>= 1)
        m = fmaxf(m, __shfl_xor_sync(0xFFFFFFFFu, m, s));

    float sum = 0.0f;
    #pragma unroll
    for (int i = 0; i < 64; ++i) {
        vals[i] = __expf(vals[i] - m);
        sum += vals[i];
    }
    #pragma unroll
    for (int s = 16; s > 0; s >>= 1)
        sum += __shfl_xor_sync(0xFFFFFFFFu, sum, s);
    const float inv = 1.0f / sum;

    #pragma unroll
    for (int c = 0; c < 8; ++c) {
        uint4 outv;
        __nv_bfloat162* po = (__nv_bfloat162*)&outv;
        #pragma unroll
        for (int i = 0; i < 4; ++i) {
            po[i].x = __float2bfloat16(vals[c * 8 + 2 * i] * inv);
            po[i].y = __float2bfloat16(vals[c * 8 + 2 * i + 1] * inv);
        }
        o[c * 32 + lane] = outv;
    }
}

// ===========================================================================
extern "C" void kernel_launch(void* const* d_in, const int* in_sizes, int n_in,
                              void* d_out, int out_size)
{
    const float* text = (const float*)d_in[0];
    const float* adj  = (const float*)d_in[1];
    const float* Wq   = (const float*)d_in[2];
    const float* bq   = (const float*)d_in[3];
    const float* Wk   = (const float*)d_in[4];
    const float* bk   = (const float*)d_in[5];
    const float* Wv   = (const float*)d_in[6];
    const float* bv   = (const float*)d_in[7];

    float* out     = (float*)d_out;
    float* new_adj = out + (long long)B_ * N_ * D_;

    bf16 *pth, *ptl, *pwth, *pwtl, *pqk, *pattn, *padjT;
    float *pvt, *ps, *pbias;
    cudaGetSymbolAddress((void**)&pth,  g_texth);
    cudaGetSymbolAddress((void**)&ptl,  g_textl);
    cudaGetSymbolAddress((void**)&pwth, g_wth);
    cudaGetSymbolAddress((void**)&pwtl, g_wtl);
    cudaGetSymbolAddress((void**)&pbias, g_bias);
    cudaGetSymbolAddress((void**)&pqk,  g_qkb);
    cudaGetSymbolAddress((void**)&pvt,  g_vt);
    cudaGetSymbolAddress((void**)&ps,   g_s);
    cudaGetSymbolAddress((void**)&pattn, g_attn);
    cudaGetSymbolAddress((void**)&padjT, g_adjT);

    bf16* psb = (bf16*)ps;

    const int SMEM_G1 = 2 * 2 * HTILE + 1024;
    cudaFuncSetAttribute((const void*)hmma_g<1, bf16>,
                         cudaFuncAttributeMaxDynamicSharedMemorySize, SMEM_G1);
    cudaFuncSetAttribute((const void*)hmma_qkv,
                         cudaFuncAttributeMaxDynamicSharedMemorySize, SMEM_QKV);
    cudaFuncSetAttribute((const void*)hmma_p4,
                         cudaFuncAttributeMaxDynamicSharedMemorySize, SMEM_P4);
    cudaFuncSetAttribute((const void*)tmma_out,
                         cudaFuncAttributeMaxDynamicSharedMemorySize, SMEM_P5T);

    const dim3 t(256);
    const long long sQK = (long long)N_ * 512;
    const long long sS  = (long long)N_ * N_;

    // prep (ONE launch): adjT + text split + W transpose/split + bias
    prep_all<<<PREP_BLOCKS, t>>>(adj, padjT, text, pth, ptl,
                                 Wq, Wk, Wv, bq, bk, bv, pwth, pwtl, pbias);

    // pass 1: fused q|k|v projection; v written directly transposed
    {
        dim3 g(768 / 128, (B_ * N_) / 128, 1);
        hmma_qkv<<<g, t, SMEM_QKV>>>(pth, ptl, pwth, pwtl, pbias, pqk, pvt);
    }

    // pass 2: S = q @ k^T -> bf16
    {
        dim3 g(N_ / 128, N_ / 128, B_);
        hmma_g<1, bf16><<<g, t, SMEM_G1>>>(
            pqk, pqk + 256, psb, D_ / 64, 512, 512, N_, sQK, sQK, sS);
    }

    // pass 3: softmax (warp per row)
    softmax_warp<<<B_ * N_ / 8, t>>>(psb, pattn, 1.0f / 16.0f);

    // pass 4: new_adj = attn @ adjT^T
    {
        dim3 g(N_ / 256, N_ / 128, B_);
        hmma_p4<<<g, t, SMEM_P4>>>(pattn, padjT, new_adj);
    }

    // pass 5: out = new_adj @ vT^T  (tf32)
    {
        dim3 g(D_ / 128, N_ / 128, B_);
        tmma_out<<<g, t, SMEM_P5T>>>(new_adj, pvt, out);
    }
}